// round 1
// baseline (speedup 1.0000x reference)
#include <cuda_runtime.h>
#include <math.h>
#include <stdint.h>

// Problem constants
#define CP_B      4
#define CP_L      8192
#define CP_D      1024
#define CP_K      2
#define CP_NF     16
#define CP_E      64              // K * 2 * NF
#define CP_BL     (CP_B * CP_L)   // 32768 tokens
#define CP_CHUNK  512
#define CP_NCHUNK (CP_L / CP_CHUNK)        // 16 chunks per sequence
#define CP_NCHTOT (CP_BL / CP_CHUNK)       // 64 chunks total

// Scratch (static device globals — no runtime allocation)
__device__ float4 g_gates[CP_BL];    // (keep0, inc0, keep1, inc1) per token
__device__ float4 g_scan[CP_BL];     // chunk-local inclusive scan (k0,i0,k1,i1)
__device__ float4 g_agg[CP_NCHTOT];  // chunk aggregate (last element of chunk scan)
__device__ float2 g_pre[CP_NCHTOT];  // counter value at chunk start (k=0, k=1)

// ---------------------------------------------------------------------------
// Kernel 1: gate projections. One warp per token; fused 4-gate weights in SMEM.
//   inc_logits -> output slot; sigmoid(inc), 1-sigmoid(reset) -> g_gates
// ---------------------------------------------------------------------------
__global__ __launch_bounds__(256) void gates_kernel(
    const float* __restrict__ x,
    const float* __restrict__ inc_w, const float* __restrict__ inc_b,
    const float* __restrict__ reset_w, const float* __restrict__ reset_b,
    float* __restrict__ out_inc_logits)
{
    __shared__ float4 sw[CP_D];  // (iw0, iw1, rw0, rw1) per d
    int tid = threadIdx.x;
    for (int d = tid; d < CP_D; d += 256) {
        sw[d] = make_float4(inc_w[d * 2 + 0], inc_w[d * 2 + 1],
                            reset_w[d * 2 + 0], reset_w[d * 2 + 1]);
    }
    __syncthreads();

    int lane = tid & 31;
    int wid  = tid >> 5;
    int tok  = blockIdx.x * 8 + wid;
    if (tok >= CP_BL) return;

    const float4* xr = reinterpret_cast<const float4*>(x + (size_t)tok * CP_D);

    float s0 = 0.f, s1 = 0.f, s2 = 0.f, s3 = 0.f;
#pragma unroll
    for (int i = 0; i < 8; ++i) {
        int i4 = lane + (i << 5);          // float4 index 0..255
        float4 xv = xr[i4];
        float4 w0 = sw[i4 * 4 + 0];
        float4 w1 = sw[i4 * 4 + 1];
        float4 w2 = sw[i4 * 4 + 2];
        float4 w3 = sw[i4 * 4 + 3];
        s0 = fmaf(xv.x, w0.x, s0); s1 = fmaf(xv.x, w0.y, s1);
        s2 = fmaf(xv.x, w0.z, s2); s3 = fmaf(xv.x, w0.w, s3);
        s0 = fmaf(xv.y, w1.x, s0); s1 = fmaf(xv.y, w1.y, s1);
        s2 = fmaf(xv.y, w1.z, s2); s3 = fmaf(xv.y, w1.w, s3);
        s0 = fmaf(xv.z, w2.x, s0); s1 = fmaf(xv.z, w2.y, s1);
        s2 = fmaf(xv.z, w2.z, s2); s3 = fmaf(xv.z, w2.w, s3);
        s0 = fmaf(xv.w, w3.x, s0); s1 = fmaf(xv.w, w3.y, s1);
        s2 = fmaf(xv.w, w3.z, s2); s3 = fmaf(xv.w, w3.w, s3);
    }
#pragma unroll
    for (int off = 16; off > 0; off >>= 1) {
        s0 += __shfl_xor_sync(0xffffffffu, s0, off);
        s1 += __shfl_xor_sync(0xffffffffu, s1, off);
        s2 += __shfl_xor_sync(0xffffffffu, s2, off);
        s3 += __shfl_xor_sync(0xffffffffu, s3, off);
    }
    if (lane == 0) {
        float il0 = s0 + inc_b[0];
        float il1 = s1 + inc_b[1];
        float rl0 = s2 + reset_b[0];
        float rl1 = s3 + reset_b[1];
        reinterpret_cast<float2*>(out_inc_logits)[tok] = make_float2(il0, il1);
        float i0 = 1.f / (1.f + expf(-il0));   // sigmoid(inc_logit)
        float i1 = 1.f / (1.f + expf(-il1));
        float k0 = 1.f / (1.f + expf(rl0));    // 1 - sigmoid(reset_logit)
        float k1 = 1.f / (1.f + expf(rl1));
        g_gates[tok] = make_float4(k0, i0, k1, i1);
    }
}

// ---------------------------------------------------------------------------
// Kernel 2: per-chunk inclusive scan of affine maps (Hillis-Steele, 512 wide).
//   combine(left,right): k = kl*kr ; i = ir + kr*il
// ---------------------------------------------------------------------------
__global__ __launch_bounds__(CP_CHUNK) void chunkscan_kernel()
{
    __shared__ float4 buf[2][CP_CHUNK];
    int t   = threadIdx.x;
    int tok = blockIdx.x * CP_CHUNK + t;

    buf[0][t] = g_gates[tok];
    __syncthreads();

    int cur = 0;
#pragma unroll
    for (int s = 1; s < CP_CHUNK; s <<= 1) {
        float4 nv = buf[cur][t];
        if (t >= s) {
            float4 lv = buf[cur][t - s];
            nv.y = fmaf(nv.x, lv.y, nv.y);  // i0 = ir + kr*il
            nv.x = nv.x * lv.x;             // k0
            nv.w = fmaf(nv.z, lv.w, nv.w);  // i1
            nv.z = nv.z * lv.z;             // k1
        }
        buf[cur ^ 1][t] = nv;
        cur ^= 1;
        __syncthreads();
    }
    float4 r = buf[cur][t];
    g_scan[tok] = r;
    if (t == CP_CHUNK - 1) g_agg[blockIdx.x] = r;
}

// ---------------------------------------------------------------------------
// Kernel 3: sequential scan over chunk aggregates (tiny: 4 seqs x 16 chunks).
//   g_pre[b][j] = counter value just before chunk j starts.
// ---------------------------------------------------------------------------
__global__ void aggscan_kernel()
{
    int b = threadIdx.x;
    if (b >= CP_B) return;
    float c0 = 0.f, c1 = 0.f;
    for (int j = 0; j < CP_NCHUNK; ++j) {
        g_pre[b * CP_NCHUNK + j] = make_float2(c0, c1);
        float4 a = g_agg[b * CP_NCHUNK + j];
        c0 = fmaf(a.x, c0, a.y);
        c1 = fmaf(a.z, c1, a.w);
    }
}

// ---------------------------------------------------------------------------
// Kernel 4: counters fixup + sinusoidal embedding + readout GEMM + bias.
//   Block = 128 tokens, 256 threads. Register tile 8 tokens x 8 cols using
//   packed fma.rn.f32x2 (2 fp32 FMA / instr on sm_103a).
// ---------------------------------------------------------------------------
#define RD_TOKS  128
#define RD_NTILE 128
#define RD_ESTR  65   // padded emb row stride

__global__ __launch_bounds__(256, 2) void readout_kernel(
    const float* __restrict__ read_w,   // (64, 1024)
    const float* __restrict__ read_b,   // (1024,)
    float* __restrict__ out_inj,        // (B*L, 1024)
    float* __restrict__ out_counters)   // (B*L, 2)
{
    __shared__ __align__(16) float s_emb[RD_TOKS * RD_ESTR];
    __shared__ __align__(16) float s_w[CP_E * RD_NTILE];

    int tid  = threadIdx.x;
    int tok0 = blockIdx.x * RD_TOKS;

    // ---- counters + embedding: thread -> (token, k) ----
    {
        int t   = tid >> 1;   // 0..127 local token
        int k   = tid & 1;
        int tok = tok0 + t;
        int b   = tok / CP_L;
        int jc  = (tok % CP_L) / CP_CHUNK;
        float2 pre = g_pre[b * CP_NCHUNK + jc];
        float4 sc  = g_scan[tok];
        float pk = k ? sc.z : sc.x;
        float pi = k ? sc.w : sc.y;
        float pp = k ? pre.y : pre.x;
        float c  = fmaf(pk, pp, pi);
        out_counters[tok * 2 + k] = c;

        float* er = s_emb + t * RD_ESTR + k * 32;
#pragma unroll
        for (int f = 0; f < CP_NF; ++f) {
            float invf = exp2f(-12.0f * (float)f / 15.0f);  // 1/4096^(f/15)
            float sv, cv;
            sincosf(c * invf, &sv, &cv);
            er[f]      = sv;
            er[16 + f] = cv;
        }
    }
    __syncthreads();

    int tx = tid & 15;       // col group (8 cols)
    int ty = tid >> 4;       // token group (8 tokens)
    const float* embp = s_emb + (ty * 8) * RD_ESTR;

    for (int nt = 0; nt < CP_D / RD_NTILE; ++nt) {
        __syncthreads();  // protect s_w reuse
        // stage 64x128 tile of read_w
#pragma unroll
        for (int i = 0; i < 8; ++i) {
            int fi = tid + i * 256;          // float4 idx 0..2047
            int j  = fi >> 5;                // row (0..63)
            int c4 = fi & 31;                // float4 col in tile
            reinterpret_cast<float4*>(s_w)[fi] =
                reinterpret_cast<const float4*>(read_w)[j * 256 + nt * 32 + c4];
        }
        __syncthreads();

        unsigned long long acc[8][4];
#pragma unroll
        for (int r = 0; r < 8; ++r)
#pragma unroll
            for (int c = 0; c < 4; ++c) acc[r][c] = 0ull;

        const ulonglong2* swp = reinterpret_cast<const ulonglong2*>(s_w);

#pragma unroll 4
        for (int j = 0; j < CP_E; ++j) {
            ulonglong2 wa = swp[j * 32 + tx * 2];      // cols 0..3 of this thread
            ulonglong2 wb = swp[j * 32 + tx * 2 + 1];  // cols 4..7
#pragma unroll
            for (int r = 0; r < 8; ++r) {
                float e = embp[r * RD_ESTR + j];
                unsigned long long ep;
                asm("mov.b64 %0, {%1, %1};" : "=l"(ep) : "f"(e));
                asm("fma.rn.f32x2 %0, %1, %2, %0;" : "+l"(acc[r][0]) : "l"(ep), "l"(wa.x));
                asm("fma.rn.f32x2 %0, %1, %2, %0;" : "+l"(acc[r][1]) : "l"(ep), "l"(wa.y));
                asm("fma.rn.f32x2 %0, %1, %2, %0;" : "+l"(acc[r][2]) : "l"(ep), "l"(wb.x));
                asm("fma.rn.f32x2 %0, %1, %2, %0;" : "+l"(acc[r][3]) : "l"(ep), "l"(wb.y));
            }
        }

        // epilogue: +bias, store
        int col = nt * RD_NTILE + tx * 8;
        float4 b0 = *reinterpret_cast<const float4*>(read_b + col);
        float4 b1 = *reinterpret_cast<const float4*>(read_b + col + 4);
#pragma unroll
        for (int r = 0; r < 8; ++r) {
            int tok = tok0 + ty * 8 + r;
            float c0 = __uint_as_float((unsigned)(acc[r][0]      )) + b0.x;
            float c1 = __uint_as_float((unsigned)(acc[r][0] >> 32)) + b0.y;
            float c2 = __uint_as_float((unsigned)(acc[r][1]      )) + b0.z;
            float c3 = __uint_as_float((unsigned)(acc[r][1] >> 32)) + b0.w;
            float c4 = __uint_as_float((unsigned)(acc[r][2]      )) + b1.x;
            float c5 = __uint_as_float((unsigned)(acc[r][2] >> 32)) + b1.y;
            float c6 = __uint_as_float((unsigned)(acc[r][3]      )) + b1.z;
            float c7 = __uint_as_float((unsigned)(acc[r][3] >> 32)) + b1.w;
            float4* orow = reinterpret_cast<float4*>(out_inj + (size_t)tok * CP_D + col);
            orow[0] = make_float4(c0, c1, c2, c3);
            orow[1] = make_float4(c4, c5, c6, c7);
        }
    }
}

// ---------------------------------------------------------------------------
// Launch
// ---------------------------------------------------------------------------
extern "C" void kernel_launch(void* const* d_in, const int* in_sizes, int n_in,
                              void* d_out, int out_size)
{
    const float* x       = (const float*)d_in[0];
    const float* inc_w   = (const float*)d_in[1];
    const float* inc_b   = (const float*)d_in[2];
    const float* reset_w = (const float*)d_in[3];
    const float* reset_b = (const float*)d_in[4];
    const float* read_w  = (const float*)d_in[5];
    const float* read_b  = (const float*)d_in[6];

    float* out        = (float*)d_out;
    float* out_inj    = out;                                   // (B,L,D)
    float* out_inclog = out + (size_t)CP_BL * CP_D;            // (B,L,K)
    float* out_cnt    = out_inclog + (size_t)CP_BL * CP_K;     // (B,L,K)

    gates_kernel<<<CP_BL / 8, 256>>>(x, inc_w, inc_b, reset_w, reset_b, out_inclog);
    chunkscan_kernel<<<CP_NCHTOT, CP_CHUNK>>>();
    aggscan_kernel<<<1, 32>>>();
    readout_kernel<<<CP_BL / RD_TOKS, 256>>>(read_w, read_b, out_inj, out_cnt);
}

// round 2
// speedup vs baseline: 1.1944x; 1.1944x over previous
#include <cuda_runtime.h>
#include <math.h>
#include <stdint.h>

// Problem constants
#define CP_B      4
#define CP_L      8192
#define CP_D      1024
#define CP_K      2
#define CP_NF     16
#define CP_E      64              // K * 2 * NF
#define CP_BL     (CP_B * CP_L)   // 32768 tokens
#define CP_CHUNK  512
#define CP_NCHUNK (CP_L / CP_CHUNK)        // 16 chunks per sequence
#define CP_NCHTOT (CP_BL / CP_CHUNK)       // 64 chunks total

// Scratch (static device globals — no runtime allocation)
__device__ float4 g_gates[CP_BL];    // (keep0, inc0, keep1, inc1) per token
__device__ float4 g_scan[CP_BL];     // chunk-local inclusive scan
__device__ float4 g_agg[CP_NCHTOT];  // chunk aggregate
__device__ float2 g_pre[CP_NCHTOT];  // counter value at chunk start

// affine compose: apply l first, then r  -> (k_r*k_l, i_r + k_r*i_l), 2 channels
__device__ __forceinline__ float4 comb(float4 l, float4 r) {
    float4 o;
    o.x = r.x * l.x;  o.y = fmaf(r.x, l.y, r.y);
    o.z = r.z * l.z;  o.w = fmaf(r.z, l.w, r.w);
    return o;
}

// ---------------------------------------------------------------------------
// Kernel 1: gate projections. One warp per 2 tokens; SoA weights in SMEM
// (float4 loads, 16B lane stride -> conflict-free).
// ---------------------------------------------------------------------------
__global__ __launch_bounds__(256) void gates_kernel(
    const float* __restrict__ x,
    const float* __restrict__ inc_w, const float* __restrict__ inc_b,
    const float* __restrict__ reset_w, const float* __restrict__ reset_b,
    float* __restrict__ out_inc_logits)
{
    __shared__ __align__(16) float sI0[CP_D], sI1[CP_D], sR0[CP_D], sR1[CP_D];
    int tid = threadIdx.x;
    for (int d = tid; d < CP_D; d += 256) {
        sI0[d] = inc_w[2 * d];     sI1[d] = inc_w[2 * d + 1];
        sR0[d] = reset_w[2 * d];   sR1[d] = reset_w[2 * d + 1];
    }
    __syncthreads();

    int lane = tid & 31;
    int wid  = tid >> 5;
    int tokA = blockIdx.x * 16 + wid * 2;
    int tokB = tokA + 1;

    const float4* xA = reinterpret_cast<const float4*>(x + (size_t)tokA * CP_D);
    const float4* xB = reinterpret_cast<const float4*>(x + (size_t)tokB * CP_D);
    const float4* wI0 = reinterpret_cast<const float4*>(sI0);
    const float4* wI1 = reinterpret_cast<const float4*>(sI1);
    const float4* wR0 = reinterpret_cast<const float4*>(sR0);
    const float4* wR1 = reinterpret_cast<const float4*>(sR1);

    float a0 = 0.f, a1 = 0.f, a2 = 0.f, a3 = 0.f;
    float b0 = 0.f, b1 = 0.f, b2 = 0.f, b3 = 0.f;
#pragma unroll
    for (int i = 0; i < 8; ++i) {
        int i4 = lane + (i << 5);
        float4 xa = xA[i4];
        float4 xb = xB[i4];
        float4 u = wI0[i4], v = wI1[i4], p = wR0[i4], q = wR1[i4];
        a0 = fmaf(xa.x, u.x, a0); a0 = fmaf(xa.y, u.y, a0);
        a0 = fmaf(xa.z, u.z, a0); a0 = fmaf(xa.w, u.w, a0);
        a1 = fmaf(xa.x, v.x, a1); a1 = fmaf(xa.y, v.y, a1);
        a1 = fmaf(xa.z, v.z, a1); a1 = fmaf(xa.w, v.w, a1);
        a2 = fmaf(xa.x, p.x, a2); a2 = fmaf(xa.y, p.y, a2);
        a2 = fmaf(xa.z, p.z, a2); a2 = fmaf(xa.w, p.w, a2);
        a3 = fmaf(xa.x, q.x, a3); a3 = fmaf(xa.y, q.y, a3);
        a3 = fmaf(xa.z, q.z, a3); a3 = fmaf(xa.w, q.w, a3);
        b0 = fmaf(xb.x, u.x, b0); b0 = fmaf(xb.y, u.y, b0);
        b0 = fmaf(xb.z, u.z, b0); b0 = fmaf(xb.w, u.w, b0);
        b1 = fmaf(xb.x, v.x, b1); b1 = fmaf(xb.y, v.y, b1);
        b1 = fmaf(xb.z, v.z, b1); b1 = fmaf(xb.w, v.w, b1);
        b2 = fmaf(xb.x, p.x, b2); b2 = fmaf(xb.y, p.y, b2);
        b2 = fmaf(xb.z, p.z, b2); b2 = fmaf(xb.w, p.w, b2);
        b3 = fmaf(xb.x, q.x, b3); b3 = fmaf(xb.y, q.y, b3);
        b3 = fmaf(xb.z, q.z, b3); b3 = fmaf(xb.w, q.w, b3);
    }
#pragma unroll
    for (int off = 16; off > 0; off >>= 1) {
        a0 += __shfl_xor_sync(0xffffffffu, a0, off);
        a1 += __shfl_xor_sync(0xffffffffu, a1, off);
        a2 += __shfl_xor_sync(0xffffffffu, a2, off);
        a3 += __shfl_xor_sync(0xffffffffu, a3, off);
        b0 += __shfl_xor_sync(0xffffffffu, b0, off);
        b1 += __shfl_xor_sync(0xffffffffu, b1, off);
        b2 += __shfl_xor_sync(0xffffffffu, b2, off);
        b3 += __shfl_xor_sync(0xffffffffu, b3, off);
    }
    if (lane == 0) {
        float ib0 = inc_b[0], ib1 = inc_b[1], rb0 = reset_b[0], rb1 = reset_b[1];
        // token A
        float ilA0 = a0 + ib0, ilA1 = a1 + ib1;
        float rlA0 = a2 + rb0, rlA1 = a3 + rb1;
        reinterpret_cast<float2*>(out_inc_logits)[tokA] = make_float2(ilA0, ilA1);
        g_gates[tokA] = make_float4(1.f / (1.f + expf(rlA0)),
                                    1.f / (1.f + expf(-ilA0)),
                                    1.f / (1.f + expf(rlA1)),
                                    1.f / (1.f + expf(-ilA1)));
        // token B
        float ilB0 = b0 + ib0, ilB1 = b1 + ib1;
        float rlB0 = b2 + rb0, rlB1 = b3 + rb1;
        reinterpret_cast<float2*>(out_inc_logits)[tokB] = make_float2(ilB0, ilB1);
        g_gates[tokB] = make_float4(1.f / (1.f + expf(rlB0)),
                                    1.f / (1.f + expf(-ilB0)),
                                    1.f / (1.f + expf(rlB1)),
                                    1.f / (1.f + expf(-ilB1)));
    }
}

// ---------------------------------------------------------------------------
// Kernel 2: per-chunk inclusive scan (shuffle-based, 2 barriers).
// 256 threads, 2 tokens/thread, chunk = 512.
// ---------------------------------------------------------------------------
__global__ __launch_bounds__(256) void chunkscan_kernel()
{
    __shared__ float4 wagg[8];
    __shared__ float4 wexc[8];
    int t = threadIdx.x, lane = t & 31, wid = t >> 5;
    int tok = blockIdx.x * CP_CHUNK + 2 * t;

    float4 a = g_gates[tok];
    float4 b = g_gates[tok + 1];
    float4 s = comb(a, b);  // thread aggregate

    // warp inclusive scan over thread aggregates
#pragma unroll
    for (int off = 1; off < 32; off <<= 1) {
        float4 l;
        l.x = __shfl_up_sync(0xffffffffu, s.x, off);
        l.y = __shfl_up_sync(0xffffffffu, s.y, off);
        l.z = __shfl_up_sync(0xffffffffu, s.z, off);
        l.w = __shfl_up_sync(0xffffffffu, s.w, off);
        if (lane >= off) s = comb(l, s);
    }
    if (lane == 31) wagg[wid] = s;
    __syncthreads();

    if (wid == 0) {
        float4 v = (lane < 8) ? wagg[lane] : make_float4(1.f, 0.f, 1.f, 0.f);
#pragma unroll
        for (int off = 1; off < 8; off <<= 1) {
            float4 l;
            l.x = __shfl_up_sync(0xffffffffu, v.x, off);
            l.y = __shfl_up_sync(0xffffffffu, v.y, off);
            l.z = __shfl_up_sync(0xffffffffu, v.z, off);
            l.w = __shfl_up_sync(0xffffffffu, v.w, off);
            if (lane >= off && lane < 8) v = comb(l, v);
        }
        if (lane == 0) wexc[0] = make_float4(1.f, 0.f, 1.f, 0.f);
        if (lane < 7)  wexc[lane + 1] = v;
    }
    __syncthreads();

    // exclusive prefix within warp
    float4 se;
    {
        float4 l;
        l.x = __shfl_up_sync(0xffffffffu, s.x, 1);
        l.y = __shfl_up_sync(0xffffffffu, s.y, 1);
        l.z = __shfl_up_sync(0xffffffffu, s.z, 1);
        l.w = __shfl_up_sync(0xffffffffu, s.w, 1);
        se = (lane == 0) ? make_float4(1.f, 0.f, 1.f, 0.f) : l;
    }
    float4 P = comb(wexc[wid], se);
    float4 o0 = comb(P, a);
    float4 o1 = comb(o0, b);
    g_scan[tok]     = o0;
    g_scan[tok + 1] = o1;
    if (t == 255) g_agg[blockIdx.x] = o1;
}

// ---------------------------------------------------------------------------
// Kernel 3: sequential scan over chunk aggregates
// ---------------------------------------------------------------------------
__global__ void aggscan_kernel()
{
    int b = threadIdx.x;
    if (b >= CP_B) return;
    float c0 = 0.f, c1 = 0.f;
    for (int j = 0; j < CP_NCHUNK; ++j) {
        g_pre[b * CP_NCHUNK + j] = make_float2(c0, c1);
        float4 a = g_agg[b * CP_NCHUNK + j];
        c0 = fmaf(a.x, c0, a.y);
        c1 = fmaf(a.z, c1, a.w);
    }
}

// ---------------------------------------------------------------------------
// Kernel 4: counters fixup + sinusoidal embedding + readout GEMM + bias.
// emb stored DUPLICATED as float2(e,e) -> no mov packing.
// Weight cols split {4tx, 64+4tx} -> conflict-free LDS.128.
// ---------------------------------------------------------------------------
#define RD_TOKS  128
#define RD_NTILE 128
#define RD_ESTR  65    // emb row stride in float2
#define RD_WSTR  132   // s_w row stride in floats

__global__ __launch_bounds__(256, 2) void readout_kernel(
    const float* __restrict__ read_w,   // (64, 1024)
    const float* __restrict__ read_b,   // (1024,)
    float* __restrict__ out_inj,        // (B*L, 1024)
    float* __restrict__ out_counters)   // (B*L, 2)
{
    __shared__ __align__(16) float2 s_emb[RD_TOKS * RD_ESTR];  // 66560 B
    __shared__ __align__(16) float  s_w[CP_E * RD_WSTR];       // 33792 B

    int tid  = threadIdx.x;
    int tok0 = blockIdx.x * RD_TOKS;

    // ---- counters + embedding (duplicated pairs) ----
    {
        int t   = tid >> 1;
        int k   = tid & 1;
        int tok = tok0 + t;
        int b   = tok / CP_L;
        int jc  = (tok % CP_L) / CP_CHUNK;
        float2 pre = g_pre[b * CP_NCHUNK + jc];
        float4 sc  = g_scan[tok];
        float pk = k ? sc.z : sc.x;
        float pi = k ? sc.w : sc.y;
        float pp = k ? pre.y : pre.x;
        float c  = fmaf(pk, pp, pi);
        out_counters[tok * 2 + k] = c;

        float2* er = s_emb + t * RD_ESTR + k * 32;
#pragma unroll
        for (int f = 0; f < CP_NF; ++f) {
            float invf = exp2f(-12.0f * (float)f / 15.0f);
            float sv, cv;
            sincosf(c * invf, &sv, &cv);
            er[f]      = make_float2(sv, sv);
            er[16 + f] = make_float2(cv, cv);
        }
    }
    __syncthreads();

    int tx = tid & 15;        // col group
    int ty = tid >> 4;        // token group (8 tokens)
    const float2* embp = s_emb + (ty * 8) * RD_ESTR;

    for (int nt = 0; nt < CP_D / RD_NTILE; ++nt) {
        if (nt) __syncthreads();
        // stage 64x128 tile of read_w (padded rows)
#pragma unroll
        for (int i = 0; i < 8; ++i) {
            int fi = tid + i * 256;          // 0..2047
            int j  = fi >> 5;                // row 0..63
            int c4 = fi & 31;                // float4 col in tile
            reinterpret_cast<float4*>(s_w + j * RD_WSTR)[c4] =
                reinterpret_cast<const float4*>(read_w)[j * 256 + nt * 32 + c4];
        }
        __syncthreads();

        unsigned long long acc[8][4];
#pragma unroll
        for (int r = 0; r < 8; ++r)
#pragma unroll
            for (int c = 0; c < 4; ++c) acc[r][c] = 0ull;

#pragma unroll 2
        for (int j = 0; j < CP_E; ++j) {
            const float* wr = s_w + j * RD_WSTR;
            ulonglong2 wa = *reinterpret_cast<const ulonglong2*>(wr + 4 * tx);       // cols 4tx..4tx+3
            ulonglong2 wb = *reinterpret_cast<const ulonglong2*>(wr + 64 + 4 * tx);  // cols 64+4tx..
#pragma unroll
            for (int r = 0; r < 8; ++r) {
                unsigned long long e =
                    *reinterpret_cast<const unsigned long long*>(&embp[r * RD_ESTR + j]);
                asm("fma.rn.f32x2 %0, %1, %2, %0;" : "+l"(acc[r][0]) : "l"(e), "l"(wa.x));
                asm("fma.rn.f32x2 %0, %1, %2, %0;" : "+l"(acc[r][1]) : "l"(e), "l"(wa.y));
                asm("fma.rn.f32x2 %0, %1, %2, %0;" : "+l"(acc[r][2]) : "l"(e), "l"(wb.x));
                asm("fma.rn.f32x2 %0, %1, %2, %0;" : "+l"(acc[r][3]) : "l"(e), "l"(wb.y));
            }
        }

        // epilogue: +bias, store (two float4 groups per row)
        int colA = nt * RD_NTILE + 4 * tx;
        int colB = colA + 64;
        float4 bA = *reinterpret_cast<const float4*>(read_b + colA);
        float4 bB = *reinterpret_cast<const float4*>(read_b + colB);
#pragma unroll
        for (int r = 0; r < 8; ++r) {
            int tok = tok0 + ty * 8 + r;
            float c0 = __uint_as_float((unsigned)(acc[r][0]      )) + bA.x;
            float c1 = __uint_as_float((unsigned)(acc[r][0] >> 32)) + bA.y;
            float c2 = __uint_as_float((unsigned)(acc[r][1]      )) + bA.z;
            float c3 = __uint_as_float((unsigned)(acc[r][1] >> 32)) + bA.w;
            float c4 = __uint_as_float((unsigned)(acc[r][2]      )) + bB.x;
            float c5 = __uint_as_float((unsigned)(acc[r][2] >> 32)) + bB.y;
            float c6 = __uint_as_float((unsigned)(acc[r][3]      )) + bB.z;
            float c7 = __uint_as_float((unsigned)(acc[r][3] >> 32)) + bB.w;
            float* orow = out_inj + (size_t)tok * CP_D;
            *reinterpret_cast<float4*>(orow + colA) = make_float4(c0, c1, c2, c3);
            *reinterpret_cast<float4*>(orow + colB) = make_float4(c4, c5, c6, c7);
        }
    }
}

// ---------------------------------------------------------------------------
// Launch
// ---------------------------------------------------------------------------
extern "C" void kernel_launch(void* const* d_in, const int* in_sizes, int n_in,
                              void* d_out, int out_size)
{
    const float* x       = (const float*)d_in[0];
    const float* inc_w   = (const float*)d_in[1];
    const float* inc_b   = (const float*)d_in[2];
    const float* reset_w = (const float*)d_in[3];
    const float* reset_b = (const float*)d_in[4];
    const float* read_w  = (const float*)d_in[5];
    const float* read_b  = (const float*)d_in[6];

    float* out        = (float*)d_out;
    float* out_inj    = out;                                   // (B,L,D)
    float* out_inclog = out + (size_t)CP_BL * CP_D;            // (B,L,K)
    float* out_cnt    = out_inclog + (size_t)CP_BL * CP_K;     // (B,L,K)

    gates_kernel<<<CP_BL / 16, 256>>>(x, inc_w, inc_b, reset_w, reset_b, out_inclog);
    chunkscan_kernel<<<CP_NCHTOT, 256>>>();
    aggscan_kernel<<<1, 32>>>();
    readout_kernel<<<CP_BL / RD_TOKS, 256>>>(read_w, read_b, out_inj, out_cnt);
}

// round 4
// speedup vs baseline: 1.9889x; 1.6652x over previous
#include <cuda_runtime.h>
#include <cuda_bf16.h>
#include <math.h>
#include <stdint.h>

// Problem constants
#define CP_B      4
#define CP_L      8192
#define CP_D      1024
#define CP_K      2
#define CP_NF     16
#define CP_E      64              // K * 2 * NF
#define CP_BL     (CP_B * CP_L)   // 32768 tokens
#define CP_CHUNK  512
#define CP_NCHUNK (CP_L / CP_CHUNK)        // 16
#define CP_NCHTOT (CP_BL / CP_CHUNK)       // 64

// Scratch (static device globals)
__device__ float4 g_gates[CP_BL];
__device__ float4 g_scan[CP_BL];
__device__ float4 g_agg[CP_NCHTOT];
__device__ float2 g_pre[CP_NCHTOT];
__device__ __align__(16) __nv_bfloat16 g_Bhi[CP_D * CP_E];  // [n][k], K-major rows of 128B
__device__ __align__(16) __nv_bfloat16 g_Blo[CP_D * CP_E];

__device__ __forceinline__ float4 comb(float4 l, float4 r) {
    float4 o;
    o.x = r.x * l.x;  o.y = fmaf(r.x, l.y, r.y);
    o.z = r.z * l.z;  o.w = fmaf(r.z, l.w, r.w);
    return o;
}

// ---------------- helpers (sm_103 base-target only: no tcgen05) ----------------
__device__ __forceinline__ uint32_t smem_u32(const void* p) {
    uint32_t a;
    asm("{ .reg .u64 t; cvta.to.shared.u64 t, %1; cvt.u32.u64 %0, t; }" : "=r"(a) : "l"(p));
    return a;
}
__device__ __forceinline__ uint32_t swz(uint32_t off) {   // SW128 swizzle (128B rows)
    return off ^ ((off >> 3) & 0x70);
}
__device__ __forceinline__ void ldsm4(uint32_t& r0, uint32_t& r1, uint32_t& r2, uint32_t& r3,
                                      uint32_t addr) {
    asm volatile("ldmatrix.sync.aligned.m8n8.x4.shared.b16 {%0,%1,%2,%3}, [%4];"
                 : "=r"(r0), "=r"(r1), "=r"(r2), "=r"(r3) : "r"(addr));
}
__device__ __forceinline__ void mma16816(float* c, const uint32_t* a, uint32_t b0, uint32_t b1) {
    asm volatile("mma.sync.aligned.m16n8k16.row.col.f32.bf16.bf16.f32 "
                 "{%0,%1,%2,%3}, {%4,%5,%6,%7}, {%8,%9}, {%0,%1,%2,%3};"
                 : "+f"(c[0]), "+f"(c[1]), "+f"(c[2]), "+f"(c[3])
                 : "r"(a[0]), "r"(a[1]), "r"(a[2]), "r"(a[3]), "r"(b0), "r"(b1));
}
__device__ __forceinline__ void cp16(uint32_t dst, const void* src) {
    asm volatile("cp.async.ca.shared.global [%0], [%1], 16;" :: "r"(dst), "l"(src));
}
__device__ __forceinline__ void cp_commit() {
    asm volatile("cp.async.commit_group;" ::: "memory");
}
template <int N>
__device__ __forceinline__ void cp_wait() {
    asm volatile("cp.async.wait_group %0;" :: "n"(N) : "memory");
}

// ---------------------------------------------------------------------------
// Kernel 0: split read_w (64,1024) fp32 -> bf16 hi/lo in [N=1024][K=64].
// ---------------------------------------------------------------------------
__global__ __launch_bounds__(256) void prep_kernel(const float* __restrict__ rw)
{
    int idx = blockIdx.x * 256 + threadIdx.x;   // 0..65535
    int n = idx >> 6, k = idx & 63;
    float v = rw[k * CP_D + n];
    __nv_bfloat16 h = __float2bfloat16(v);
    float res = v - __bfloat162float(h);
    g_Bhi[n * CP_E + k] = h;
    g_Blo[n * CP_E + k] = __float2bfloat16(res);
}

// ---------------------------------------------------------------------------
// Kernel 1: gate projections (unchanged)
// ---------------------------------------------------------------------------
__global__ __launch_bounds__(256) void gates_kernel(
    const float* __restrict__ x,
    const float* __restrict__ inc_w, const float* __restrict__ inc_b,
    const float* __restrict__ reset_w, const float* __restrict__ reset_b,
    float* __restrict__ out_inc_logits)
{
    __shared__ __align__(16) float sI0[CP_D], sI1[CP_D], sR0[CP_D], sR1[CP_D];
    int tid = threadIdx.x;
    for (int d = tid; d < CP_D; d += 256) {
        sI0[d] = inc_w[2 * d];     sI1[d] = inc_w[2 * d + 1];
        sR0[d] = reset_w[2 * d];   sR1[d] = reset_w[2 * d + 1];
    }
    __syncthreads();

    int lane = tid & 31;
    int wid  = tid >> 5;
    int tokA = blockIdx.x * 16 + wid * 2;
    int tokB = tokA + 1;

    const float4* xA = reinterpret_cast<const float4*>(x + (size_t)tokA * CP_D);
    const float4* xB = reinterpret_cast<const float4*>(x + (size_t)tokB * CP_D);
    const float4* wI0 = reinterpret_cast<const float4*>(sI0);
    const float4* wI1 = reinterpret_cast<const float4*>(sI1);
    const float4* wR0 = reinterpret_cast<const float4*>(sR0);
    const float4* wR1 = reinterpret_cast<const float4*>(sR1);

    float a0 = 0.f, a1 = 0.f, a2 = 0.f, a3 = 0.f;
    float b0 = 0.f, b1 = 0.f, b2 = 0.f, b3 = 0.f;
#pragma unroll
    for (int i = 0; i < 8; ++i) {
        int i4 = lane + (i << 5);
        float4 xa = xA[i4];
        float4 xb = xB[i4];
        float4 u = wI0[i4], v = wI1[i4], p = wR0[i4], q = wR1[i4];
        a0 = fmaf(xa.x, u.x, a0); a0 = fmaf(xa.y, u.y, a0);
        a0 = fmaf(xa.z, u.z, a0); a0 = fmaf(xa.w, u.w, a0);
        a1 = fmaf(xa.x, v.x, a1); a1 = fmaf(xa.y, v.y, a1);
        a1 = fmaf(xa.z, v.z, a1); a1 = fmaf(xa.w, v.w, a1);
        a2 = fmaf(xa.x, p.x, a2); a2 = fmaf(xa.y, p.y, a2);
        a2 = fmaf(xa.z, p.z, a2); a2 = fmaf(xa.w, p.w, a2);
        a3 = fmaf(xa.x, q.x, a3); a3 = fmaf(xa.y, q.y, a3);
        a3 = fmaf(xa.z, q.z, a3); a3 = fmaf(xa.w, q.w, a3);
        b0 = fmaf(xb.x, u.x, b0); b0 = fmaf(xb.y, u.y, b0);
        b0 = fmaf(xb.z, u.z, b0); b0 = fmaf(xb.w, u.w, b0);
        b1 = fmaf(xb.x, v.x, b1); b1 = fmaf(xb.y, v.y, b1);
        b1 = fmaf(xb.z, v.z, b1); b1 = fmaf(xb.w, v.w, b1);
        b2 = fmaf(xb.x, p.x, b2); b2 = fmaf(xb.y, p.y, b2);
        b2 = fmaf(xb.z, p.z, b2); b2 = fmaf(xb.w, p.w, b2);
        b3 = fmaf(xb.x, q.x, b3); b3 = fmaf(xb.y, q.y, b3);
        b3 = fmaf(xb.z, q.z, b3); b3 = fmaf(xb.w, q.w, b3);
    }
#pragma unroll
    for (int off = 16; off > 0; off >>= 1) {
        a0 += __shfl_xor_sync(0xffffffffu, a0, off);
        a1 += __shfl_xor_sync(0xffffffffu, a1, off);
        a2 += __shfl_xor_sync(0xffffffffu, a2, off);
        a3 += __shfl_xor_sync(0xffffffffu, a3, off);
        b0 += __shfl_xor_sync(0xffffffffu, b0, off);
        b1 += __shfl_xor_sync(0xffffffffu, b1, off);
        b2 += __shfl_xor_sync(0xffffffffu, b2, off);
        b3 += __shfl_xor_sync(0xffffffffu, b3, off);
    }
    if (lane == 0) {
        float ib0 = inc_b[0], ib1 = inc_b[1], rb0 = reset_b[0], rb1 = reset_b[1];
        float ilA0 = a0 + ib0, ilA1 = a1 + ib1;
        float rlA0 = a2 + rb0, rlA1 = a3 + rb1;
        reinterpret_cast<float2*>(out_inc_logits)[tokA] = make_float2(ilA0, ilA1);
        g_gates[tokA] = make_float4(1.f / (1.f + expf(rlA0)),
                                    1.f / (1.f + expf(-ilA0)),
                                    1.f / (1.f + expf(rlA1)),
                                    1.f / (1.f + expf(-ilA1)));
        float ilB0 = b0 + ib0, ilB1 = b1 + ib1;
        float rlB0 = b2 + rb0, rlB1 = b3 + rb1;
        reinterpret_cast<float2*>(out_inc_logits)[tokB] = make_float2(ilB0, ilB1);
        g_gates[tokB] = make_float4(1.f / (1.f + expf(rlB0)),
                                    1.f / (1.f + expf(-ilB0)),
                                    1.f / (1.f + expf(rlB1)),
                                    1.f / (1.f + expf(-ilB1)));
    }
}

// ---------------------------------------------------------------------------
// Kernel 2: per-chunk inclusive scan (unchanged)
// ---------------------------------------------------------------------------
__global__ __launch_bounds__(256) void chunkscan_kernel()
{
    __shared__ float4 wagg[8];
    __shared__ float4 wexc[8];
    int t = threadIdx.x, lane = t & 31, wid = t >> 5;
    int tok = blockIdx.x * CP_CHUNK + 2 * t;

    float4 a = g_gates[tok];
    float4 b = g_gates[tok + 1];
    float4 s = comb(a, b);

#pragma unroll
    for (int off = 1; off < 32; off <<= 1) {
        float4 l;
        l.x = __shfl_up_sync(0xffffffffu, s.x, off);
        l.y = __shfl_up_sync(0xffffffffu, s.y, off);
        l.z = __shfl_up_sync(0xffffffffu, s.z, off);
        l.w = __shfl_up_sync(0xffffffffu, s.w, off);
        if (lane >= off) s = comb(l, s);
    }
    if (lane == 31) wagg[wid] = s;
    __syncthreads();

    if (wid == 0) {
        float4 v = (lane < 8) ? wagg[lane] : make_float4(1.f, 0.f, 1.f, 0.f);
#pragma unroll
        for (int off = 1; off < 8; off <<= 1) {
            float4 l;
            l.x = __shfl_up_sync(0xffffffffu, v.x, off);
            l.y = __shfl_up_sync(0xffffffffu, v.y, off);
            l.z = __shfl_up_sync(0xffffffffu, v.z, off);
            l.w = __shfl_up_sync(0xffffffffu, v.w, off);
            if (lane >= off && lane < 8) v = comb(l, v);
        }
        if (lane == 0) wexc[0] = make_float4(1.f, 0.f, 1.f, 0.f);
        if (lane < 7)  wexc[lane + 1] = v;
    }
    __syncthreads();

    float4 se;
    {
        float4 l;
        l.x = __shfl_up_sync(0xffffffffu, s.x, 1);
        l.y = __shfl_up_sync(0xffffffffu, s.y, 1);
        l.z = __shfl_up_sync(0xffffffffu, s.z, 1);
        l.w = __shfl_up_sync(0xffffffffu, s.w, 1);
        se = (lane == 0) ? make_float4(1.f, 0.f, 1.f, 0.f) : l;
    }
    float4 P = comb(wexc[wid], se);
    float4 o0 = comb(P, a);
    float4 o1 = comb(o0, b);
    g_scan[tok]     = o0;
    g_scan[tok + 1] = o1;
    if (t == 255) g_agg[blockIdx.x] = o1;
}

// ---------------------------------------------------------------------------
// Kernel 3: sequential scan over chunk aggregates
// ---------------------------------------------------------------------------
__global__ void aggscan_kernel()
{
    int b = threadIdx.x;
    if (b >= CP_B) return;
    float c0 = 0.f, c1 = 0.f;
    for (int j = 0; j < CP_NCHUNK; ++j) {
        g_pre[b * CP_NCHUNK + j] = make_float2(c0, c1);
        float4 a = g_agg[b * CP_NCHUNK + j];
        c0 = fmaf(a.x, c0, a.y);
        c1 = fmaf(a.z, c1, a.w);
    }
}

// ---------------------------------------------------------------------------
// Kernel 4: counters + embedding + mma.sync bf16x3 GEMM + bias.
// 256 threads / 8 warps, 128 tokens per block. Warp w: tokens 16w..16w+15,
// all 128 cols of the current N-chunk. 8 N-chunks, B double-buffered cp.async.
// ---------------------------------------------------------------------------
#define SMB_BIAS  0
#define SMB_EHI   4096
#define SMB_ELO   20480
#define SMB_B     36864
#define SMB_BUF   32768
#define SM_TOT    (SMB_B + 2 * SMB_BUF)   // 102400

__device__ __forceinline__ void stage_B(uint32_t sb, int nt, int buf, int tid)
{
    const char* srcH = (const char*)g_Bhi + (size_t)nt * 128 * 128;
    const char* srcL = (const char*)g_Blo + (size_t)nt * 128 * 128;
    uint32_t dstH = sb + SMB_B + buf * SMB_BUF;
    uint32_t dstL = dstH + 16384;
#pragma unroll
    for (int m = 0; m < 4; ++m) {
        int idx = tid + m * 256;          // 0..1023
        int nl = idx >> 3, c16 = idx & 7;
        uint32_t sw = swz((uint32_t)(nl * 128 + c16 * 16));
        cp16(dstH + sw, srcH + nl * 128 + c16 * 16);
        cp16(dstL + sw, srcL + nl * 128 + c16 * 16);
    }
}

__global__ __launch_bounds__(256, 2) void readout_kernel(
    const float* __restrict__ read_b,
    float* __restrict__ out_inj,        // (B*L, 1024)
    float* __restrict__ out_counters)   // (B*L, 2)
{
    extern __shared__ __align__(1024) char smem[];
    uint32_t sb = smem_u32(smem);
    int tid = threadIdx.x, lane = tid & 31, w = tid >> 5;
    int tok0 = blockIdx.x * 128;

    // bias -> smem (256 * 16B = 4KB)
    reinterpret_cast<float4*>(smem + SMB_BIAS)[tid] =
        reinterpret_cast<const float4*>(read_b)[tid];

    // ---- counters + embedding -> bf16 hi/lo swizzled tiles [128 x 64] ----
    {
        int t   = tid >> 1;
        int k   = tid & 1;
        int tok = tok0 + t;
        int b   = tok / CP_L;
        int jc  = (tok % CP_L) / CP_CHUNK;
        float2 pre = g_pre[b * CP_NCHUNK + jc];
        float4 sc  = g_scan[tok];
        float pk = k ? sc.z : sc.x;
        float pi = k ? sc.w : sc.y;
        float pp = k ? pre.y : pre.x;
        float c  = fmaf(pk, pp, pi);
        out_counters[tok * 2 + k] = c;

        float sv[16], cv[16];
#pragma unroll
        for (int f = 0; f < CP_NF; ++f) {
            float invf = exp2f(-12.0f * (float)f / 15.0f);
            sincosf(c * invf, &sv[f], &cv[f]);
        }
#pragma unroll
        for (int q = 0; q < 8; ++q) {     // 8B = 4 bf16 per store
            unsigned long long hi = 0ull, lo = 0ull;
#pragma unroll
            for (int bq = 0; bq < 4; ++bq) {
                int j = 4 * q + bq;                       // 0..31 within this k half
                float v = (j < 16) ? sv[j] : cv[j - 16];
                __nv_bfloat16 h = __float2bfloat16(v);
                float res = v - __bfloat162float(h);
                __nv_bfloat16 l = __float2bfloat16(res);
                hi |= (unsigned long long)__bfloat16_as_ushort(h) << (16 * bq);
                lo |= (unsigned long long)__bfloat16_as_ushort(l) << (16 * bq);
            }
            uint32_t off = (uint32_t)(t * 128 + k * 64 + q * 8);
            uint32_t sw = swz(off);
            *reinterpret_cast<unsigned long long*>(smem + SMB_EHI + sw) = hi;
            *reinterpret_cast<unsigned long long*>(smem + SMB_ELO + sw) = lo;
        }
    }

    // prefetch B chunk 0
    stage_B(sb, 0, 0, tid);
    cp_commit();

    int row = lane >> 2, tcol = 2 * (lane & 3);

#pragma unroll 1
    for (int nt = 0; nt < 8; ++nt) {
        int buf = nt & 1;
        if (nt < 7) {
            stage_B(sb, nt + 1, buf ^ 1, tid);
            cp_commit();
            cp_wait<1>();
        } else {
            cp_wait<0>();
        }
        __syncthreads();

        uint32_t bbase = sb + SMB_B + buf * SMB_BUF;
        float acc[16][4];
#pragma unroll
        for (int p = 0; p < 16; ++p)
#pragma unroll
            for (int i = 0; i < 4; ++i) acc[p][i] = 0.f;

#pragma unroll
        for (int kk = 0; kk < 4; ++kk) {
            uint32_t ah[4], al[4];
            {
                int m = lane >> 3, r = lane & 7;
                uint32_t aoff = swz((uint32_t)((w * 16 + (m & 1) * 8 + r) * 128 +
                                               (2 * kk + (m >> 1)) * 16));
                ldsm4(ah[0], ah[1], ah[2], ah[3], sb + SMB_EHI + aoff);
                ldsm4(al[0], al[1], al[2], al[3], sb + SMB_ELO + aoff);
            }
#pragma unroll
            for (int p = 0; p < 8; ++p) {
                uint32_t bh[4], bl[4];
                int m = lane >> 3, r = lane & 7;
                uint32_t boff = swz((uint32_t)((p * 16 + (m >> 1) * 8 + r) * 128 +
                                               (2 * kk + (m & 1)) * 16));
                ldsm4(bh[0], bh[1], bh[2], bh[3], bbase + boff);
                ldsm4(bl[0], bl[1], bl[2], bl[3], bbase + 16384 + boff);
                mma16816(acc[2 * p],     ah, bh[0], bh[1]);
                mma16816(acc[2 * p + 1], ah, bh[2], bh[3]);
                mma16816(acc[2 * p],     ah, bl[0], bl[1]);
                mma16816(acc[2 * p + 1], ah, bl[2], bl[3]);
                mma16816(acc[2 * p],     al, bh[0], bh[1]);
                mma16816(acc[2 * p + 1], al, bh[2], bh[3]);
            }
        }

        // epilogue: +bias, store 16 tokens x 128 cols per warp
        const float* sbias = reinterpret_cast<const float*>(smem + SMB_BIAS) + nt * 128;
        float* o0 = out_inj + (size_t)(tok0 + w * 16 + row) * CP_D + nt * 128;
        float* o1 = o0 + 8 * CP_D;
#pragma unroll
        for (int p = 0; p < 16; ++p) {
            int col = p * 8 + tcol;
            float2 bv = *reinterpret_cast<const float2*>(sbias + col);
            *reinterpret_cast<float2*>(o0 + col) =
                make_float2(acc[p][0] + bv.x, acc[p][1] + bv.y);
            *reinterpret_cast<float2*>(o1 + col) =
                make_float2(acc[p][2] + bv.x, acc[p][3] + bv.y);
        }
        __syncthreads();
    }
}

// ---------------------------------------------------------------------------
// Launch
// ---------------------------------------------------------------------------
extern "C" void kernel_launch(void* const* d_in, const int* in_sizes, int n_in,
                              void* d_out, int out_size)
{
    const float* x       = (const float*)d_in[0];
    const float* inc_w   = (const float*)d_in[1];
    const float* inc_b   = (const float*)d_in[2];
    const float* reset_w = (const float*)d_in[3];
    const float* reset_b = (const float*)d_in[4];
    const float* read_w  = (const float*)d_in[5];
    const float* read_b  = (const float*)d_in[6];

    float* out        = (float*)d_out;
    float* out_inj    = out;
    float* out_inclog = out + (size_t)CP_BL * CP_D;
    float* out_cnt    = out_inclog + (size_t)CP_BL * CP_K;

    cudaFuncSetAttribute(readout_kernel,
                         cudaFuncAttributeMaxDynamicSharedMemorySize, SM_TOT);

    prep_kernel<<<256, 256>>>(read_w);
    gates_kernel<<<CP_BL / 16, 256>>>(x, inc_w, inc_b, reset_w, reset_b, out_inclog);
    chunkscan_kernel<<<CP_NCHTOT, 256>>>();
    aggscan_kernel<<<1, 32>>>();
    readout_kernel<<<CP_BL / 128, 256, SM_TOT>>>(read_b, out_inj, out_cnt);
}

// round 5
// speedup vs baseline: 2.0823x; 1.0470x over previous
#include <cuda_runtime.h>
#include <cuda_bf16.h>
#include <math.h>
#include <stdint.h>

// Problem constants
#define CP_B      4
#define CP_L      8192
#define CP_D      1024
#define CP_K      2
#define CP_NF     16
#define CP_E      64              // K * 2 * NF
#define CP_BL     (CP_B * CP_L)   // 32768 tokens
#define CP_CHUNK  512
#define CP_NCHUNK (CP_L / CP_CHUNK)        // 16
#define CP_NCHTOT (CP_BL / CP_CHUNK)       // 64

// Scratch (static device globals)
__device__ float4 g_gates[CP_BL];
__device__ float4 g_scan[CP_BL];
__device__ float4 g_agg[CP_NCHTOT];
__device__ float2 g_pre[CP_NCHTOT];
__device__ int    g_sync;                                   // zero-initialized
__device__ __align__(16) __nv_bfloat16 g_Bhi[CP_D * CP_E];  // [n][k], K-major rows of 128B
__device__ __align__(16) __nv_bfloat16 g_Blo[CP_D * CP_E];

__device__ __forceinline__ float4 comb(float4 l, float4 r) {
    float4 o;
    o.x = r.x * l.x;  o.y = fmaf(r.x, l.y, r.y);
    o.z = r.z * l.z;  o.w = fmaf(r.z, l.w, r.w);
    return o;
}

// ---------------- helpers (sm_103 base-target only: no tcgen05) ----------------
__device__ __forceinline__ uint32_t smem_u32(const void* p) {
    uint32_t a;
    asm("{ .reg .u64 t; cvta.to.shared.u64 t, %1; cvt.u32.u64 %0, t; }" : "=r"(a) : "l"(p));
    return a;
}
__device__ __forceinline__ uint32_t swz(uint32_t off) {   // SW128 swizzle (128B rows)
    return off ^ ((off >> 3) & 0x70);
}
__device__ __forceinline__ void ldsm4(uint32_t& r0, uint32_t& r1, uint32_t& r2, uint32_t& r3,
                                      uint32_t addr) {
    asm volatile("ldmatrix.sync.aligned.m8n8.x4.shared.b16 {%0,%1,%2,%3}, [%4];"
                 : "=r"(r0), "=r"(r1), "=r"(r2), "=r"(r3) : "r"(addr));
}
__device__ __forceinline__ void mma16816(float* c, const uint32_t* a, uint32_t b0, uint32_t b1) {
    asm volatile("mma.sync.aligned.m16n8k16.row.col.f32.bf16.bf16.f32 "
                 "{%0,%1,%2,%3}, {%4,%5,%6,%7}, {%8,%9}, {%0,%1,%2,%3};"
                 : "+f"(c[0]), "+f"(c[1]), "+f"(c[2]), "+f"(c[3])
                 : "r"(a[0]), "r"(a[1]), "r"(a[2]), "r"(a[3]), "r"(b0), "r"(b1));
}
__device__ __forceinline__ void cp16(uint32_t dst, const void* src) {
    asm volatile("cp.async.ca.shared.global [%0], [%1], 16;" :: "r"(dst), "l"(src));
}
__device__ __forceinline__ void cp_commit() {
    asm volatile("cp.async.commit_group;" ::: "memory");
}
template <int N>
__device__ __forceinline__ void cp_wait() {
    asm volatile("cp.async.wait_group %0;" :: "n"(N) : "memory");
}

// ---------------------------------------------------------------------------
// Kernel 0: split read_w (64,1024) fp32 -> bf16 hi/lo in [N=1024][K=64].
// ---------------------------------------------------------------------------
__global__ __launch_bounds__(256) void prep_kernel(const float* __restrict__ rw)
{
    int idx = blockIdx.x * 256 + threadIdx.x;   // 0..65535
    int n = idx >> 6, k = idx & 63;
    float v = rw[k * CP_D + n];
    __nv_bfloat16 h = __float2bfloat16(v);
    float res = v - __bfloat162float(h);
    g_Bhi[n * CP_E + k] = h;
    g_Blo[n * CP_E + k] = __float2bfloat16(res);
}

// ---------------------------------------------------------------------------
// Kernel 1: gate projections (x loads use streaming hint)
// ---------------------------------------------------------------------------
__global__ __launch_bounds__(256) void gates_kernel(
    const float* __restrict__ x,
    const float* __restrict__ inc_w, const float* __restrict__ inc_b,
    const float* __restrict__ reset_w, const float* __restrict__ reset_b,
    float* __restrict__ out_inc_logits)
{
    __shared__ __align__(16) float sI0[CP_D], sI1[CP_D], sR0[CP_D], sR1[CP_D];
    int tid = threadIdx.x;
    for (int d = tid; d < CP_D; d += 256) {
        sI0[d] = inc_w[2 * d];     sI1[d] = inc_w[2 * d + 1];
        sR0[d] = reset_w[2 * d];   sR1[d] = reset_w[2 * d + 1];
    }
    __syncthreads();

    int lane = tid & 31;
    int wid  = tid >> 5;
    int tokA = blockIdx.x * 16 + wid * 2;
    int tokB = tokA + 1;

    const float4* xA = reinterpret_cast<const float4*>(x + (size_t)tokA * CP_D);
    const float4* xB = reinterpret_cast<const float4*>(x + (size_t)tokB * CP_D);
    const float4* wI0 = reinterpret_cast<const float4*>(sI0);
    const float4* wI1 = reinterpret_cast<const float4*>(sI1);
    const float4* wR0 = reinterpret_cast<const float4*>(sR0);
    const float4* wR1 = reinterpret_cast<const float4*>(sR1);

    float a0 = 0.f, a1 = 0.f, a2 = 0.f, a3 = 0.f;
    float b0 = 0.f, b1 = 0.f, b2 = 0.f, b3 = 0.f;
#pragma unroll
    for (int i = 0; i < 8; ++i) {
        int i4 = lane + (i << 5);
        float4 xa = __ldcs(&xA[i4]);
        float4 xb = __ldcs(&xB[i4]);
        float4 u = wI0[i4], v = wI1[i4], p = wR0[i4], q = wR1[i4];
        a0 = fmaf(xa.x, u.x, a0); a0 = fmaf(xa.y, u.y, a0);
        a0 = fmaf(xa.z, u.z, a0); a0 = fmaf(xa.w, u.w, a0);
        a1 = fmaf(xa.x, v.x, a1); a1 = fmaf(xa.y, v.y, a1);
        a1 = fmaf(xa.z, v.z, a1); a1 = fmaf(xa.w, v.w, a1);
        a2 = fmaf(xa.x, p.x, a2); a2 = fmaf(xa.y, p.y, a2);
        a2 = fmaf(xa.z, p.z, a2); a2 = fmaf(xa.w, p.w, a2);
        a3 = fmaf(xa.x, q.x, a3); a3 = fmaf(xa.y, q.y, a3);
        a3 = fmaf(xa.z, q.z, a3); a3 = fmaf(xa.w, q.w, a3);
        b0 = fmaf(xb.x, u.x, b0); b0 = fmaf(xb.y, u.y, b0);
        b0 = fmaf(xb.z, u.z, b0); b0 = fmaf(xb.w, u.w, b0);
        b1 = fmaf(xb.x, v.x, b1); b1 = fmaf(xb.y, v.y, b1);
        b1 = fmaf(xb.z, v.z, b1); b1 = fmaf(xb.w, v.w, b1);
        b2 = fmaf(xb.x, p.x, b2); b2 = fmaf(xb.y, p.y, b2);
        b2 = fmaf(xb.z, p.z, b2); b2 = fmaf(xb.w, p.w, b2);
        b3 = fmaf(xb.x, q.x, b3); b3 = fmaf(xb.y, q.y, b3);
        b3 = fmaf(xb.z, q.z, b3); b3 = fmaf(xb.w, q.w, b3);
    }
#pragma unroll
    for (int off = 16; off > 0; off >>= 1) {
        a0 += __shfl_xor_sync(0xffffffffu, a0, off);
        a1 += __shfl_xor_sync(0xffffffffu, a1, off);
        a2 += __shfl_xor_sync(0xffffffffu, a2, off);
        a3 += __shfl_xor_sync(0xffffffffu, a3, off);
        b0 += __shfl_xor_sync(0xffffffffu, b0, off);
        b1 += __shfl_xor_sync(0xffffffffu, b1, off);
        b2 += __shfl_xor_sync(0xffffffffu, b2, off);
        b3 += __shfl_xor_sync(0xffffffffu, b3, off);
    }
    if (lane == 0) {
        float ib0 = inc_b[0], ib1 = inc_b[1], rb0 = reset_b[0], rb1 = reset_b[1];
        float ilA0 = a0 + ib0, ilA1 = a1 + ib1;
        float rlA0 = a2 + rb0, rlA1 = a3 + rb1;
        reinterpret_cast<float2*>(out_inc_logits)[tokA] = make_float2(ilA0, ilA1);
        g_gates[tokA] = make_float4(1.f / (1.f + expf(rlA0)),
                                    1.f / (1.f + expf(-ilA0)),
                                    1.f / (1.f + expf(rlA1)),
                                    1.f / (1.f + expf(-ilA1)));
        float ilB0 = b0 + ib0, ilB1 = b1 + ib1;
        float rlB0 = b2 + rb0, rlB1 = b3 + rb1;
        reinterpret_cast<float2*>(out_inc_logits)[tokB] = make_float2(ilB0, ilB1);
        g_gates[tokB] = make_float4(1.f / (1.f + expf(rlB0)),
                                    1.f / (1.f + expf(-ilB0)),
                                    1.f / (1.f + expf(rlB1)),
                                    1.f / (1.f + expf(-ilB1)));
    }
}

// ---------------------------------------------------------------------------
// Kernel 2: per-chunk inclusive scan + fused aggregate scan in the tail.
// Last block to finish (atomic election) computes g_pre and resets the counter.
// ---------------------------------------------------------------------------
__global__ __launch_bounds__(256) void chunkscan_kernel()
{
    __shared__ float4 wagg[8];
    __shared__ float4 wexc[8];
    __shared__ int s_last;
    int t = threadIdx.x, lane = t & 31, wid = t >> 5;
    int tok = blockIdx.x * CP_CHUNK + 2 * t;

    float4 a = g_gates[tok];
    float4 b = g_gates[tok + 1];
    float4 s = comb(a, b);

#pragma unroll
    for (int off = 1; off < 32; off <<= 1) {
        float4 l;
        l.x = __shfl_up_sync(0xffffffffu, s.x, off);
        l.y = __shfl_up_sync(0xffffffffu, s.y, off);
        l.z = __shfl_up_sync(0xffffffffu, s.z, off);
        l.w = __shfl_up_sync(0xffffffffu, s.w, off);
        if (lane >= off) s = comb(l, s);
    }
    if (lane == 31) wagg[wid] = s;
    __syncthreads();

    if (wid == 0) {
        float4 v = (lane < 8) ? wagg[lane] : make_float4(1.f, 0.f, 1.f, 0.f);
#pragma unroll
        for (int off = 1; off < 8; off <<= 1) {
            float4 l;
            l.x = __shfl_up_sync(0xffffffffu, v.x, off);
            l.y = __shfl_up_sync(0xffffffffu, v.y, off);
            l.z = __shfl_up_sync(0xffffffffu, v.z, off);
            l.w = __shfl_up_sync(0xffffffffu, v.w, off);
            if (lane >= off && lane < 8) v = comb(l, v);
        }
        if (lane == 0) wexc[0] = make_float4(1.f, 0.f, 1.f, 0.f);
        if (lane < 7)  wexc[lane + 1] = v;
    }
    __syncthreads();

    float4 se;
    {
        float4 l;
        l.x = __shfl_up_sync(0xffffffffu, s.x, 1);
        l.y = __shfl_up_sync(0xffffffffu, s.y, 1);
        l.z = __shfl_up_sync(0xffffffffu, s.z, 1);
        l.w = __shfl_up_sync(0xffffffffu, s.w, 1);
        se = (lane == 0) ? make_float4(1.f, 0.f, 1.f, 0.f) : l;
    }
    float4 P = comb(wexc[wid], se);
    float4 o0 = comb(P, a);
    float4 o1 = comb(o0, b);
    g_scan[tok]     = o0;
    g_scan[tok + 1] = o1;
    if (t == 255) g_agg[blockIdx.x] = o1;

    // ---- fused aggregate scan: last block to arrive does the 64-chunk scan ----
    __threadfence();
    __syncthreads();
    if (t == 0) {
        int prev = atomicAdd(&g_sync, 1);
        s_last = (prev == CP_NCHTOT - 1);
    }
    __syncthreads();
    if (s_last) {
        if (t < CP_B) {
            float c0 = 0.f, c1 = 0.f;
            for (int j = 0; j < CP_NCHUNK; ++j) {
                g_pre[t * CP_NCHUNK + j] = make_float2(c0, c1);
                float4 ag = g_agg[t * CP_NCHUNK + j];
                c0 = fmaf(ag.x, c0, ag.y);
                c1 = fmaf(ag.z, c1, ag.w);
            }
        }
        if (t == 0) g_sync = 0;   // reset for next graph replay
    }
}

// ---------------------------------------------------------------------------
// Kernel 4: counters + embedding + mma.sync bf16x3 GEMM + bias.
// 256 threads / 8 warps, 128 tokens per block. Warp w: tokens 16w..16w+15,
// all 128 cols of the current N-chunk. 8 N-chunks, B double-buffered cp.async.
// ---------------------------------------------------------------------------
#define SMB_BIAS  0
#define SMB_EHI   4096
#define SMB_ELO   20480
#define SMB_B     36864
#define SMB_BUF   32768
#define SM_TOT    (SMB_B + 2 * SMB_BUF)   // 102400

__device__ __forceinline__ void stage_B(uint32_t sb, int nt, int buf, int tid)
{
    const char* srcH = (const char*)g_Bhi + (size_t)nt * 128 * 128;
    const char* srcL = (const char*)g_Blo + (size_t)nt * 128 * 128;
    uint32_t dstH = sb + SMB_B + buf * SMB_BUF;
    uint32_t dstL = dstH + 16384;
#pragma unroll
    for (int m = 0; m < 4; ++m) {
        int idx = tid + m * 256;          // 0..1023
        int nl = idx >> 3, c16 = idx & 7;
        uint32_t sw = swz((uint32_t)(nl * 128 + c16 * 16));
        cp16(dstH + sw, srcH + nl * 128 + c16 * 16);
        cp16(dstL + sw, srcL + nl * 128 + c16 * 16);
    }
}

__global__ __launch_bounds__(256, 2) void readout_kernel(
    const float* __restrict__ read_b,
    float* __restrict__ out_inj,        // (B*L, 1024)
    float* __restrict__ out_counters)   // (B*L, 2)
{
    extern __shared__ __align__(1024) char smem[];
    uint32_t sb = smem_u32(smem);
    int tid = threadIdx.x, lane = tid & 31, w = tid >> 5;
    int tok0 = blockIdx.x * 128;

    // bias -> smem (256 * 16B = 4KB)
    reinterpret_cast<float4*>(smem + SMB_BIAS)[tid] =
        reinterpret_cast<const float4*>(read_b)[tid];

    // ---- counters + embedding -> bf16 hi/lo swizzled tiles [128 x 64] ----
    {
        int t   = tid >> 1;
        int k   = tid & 1;
        int tok = tok0 + t;
        int b   = tok / CP_L;
        int jc  = (tok % CP_L) / CP_CHUNK;
        float2 pre = g_pre[b * CP_NCHUNK + jc];
        float4 sc  = g_scan[tok];
        float pk = k ? sc.z : sc.x;
        float pi = k ? sc.w : sc.y;
        float pp = k ? pre.y : pre.x;
        float c  = fmaf(pk, pp, pi);
        out_counters[tok * 2 + k] = c;

        float sv[16], cv[16];
#pragma unroll
        for (int f = 0; f < CP_NF; ++f) {
            float invf = exp2f(-12.0f * (float)f / 15.0f);
            sincosf(c * invf, &sv[f], &cv[f]);
        }
#pragma unroll
        for (int q = 0; q < 8; ++q) {     // 8B = 4 bf16 per store
            unsigned long long hi = 0ull, lo = 0ull;
#pragma unroll
            for (int bq = 0; bq < 4; ++bq) {
                int j = 4 * q + bq;                       // 0..31 within this k half
                float v = (j < 16) ? sv[j] : cv[j - 16];
                __nv_bfloat16 h = __float2bfloat16(v);
                float res = v - __bfloat162float(h);
                __nv_bfloat16 l = __float2bfloat16(res);
                hi |= (unsigned long long)__bfloat16_as_ushort(h) << (16 * bq);
                lo |= (unsigned long long)__bfloat16_as_ushort(l) << (16 * bq);
            }
            uint32_t off = (uint32_t)(t * 128 + k * 64 + q * 8);
            uint32_t sw = swz(off);
            *reinterpret_cast<unsigned long long*>(smem + SMB_EHI + sw) = hi;
            *reinterpret_cast<unsigned long long*>(smem + SMB_ELO + sw) = lo;
        }
    }

    // prefetch B chunk 0
    stage_B(sb, 0, 0, tid);
    cp_commit();

    int row = lane >> 2, tcol = 2 * (lane & 3);

#pragma unroll 1
    for (int nt = 0; nt < 8; ++nt) {
        int buf = nt & 1;
        if (nt < 7) {
            stage_B(sb, nt + 1, buf ^ 1, tid);
            cp_commit();
            cp_wait<1>();
        } else {
            cp_wait<0>();
        }
        __syncthreads();

        uint32_t bbase = sb + SMB_B + buf * SMB_BUF;
        float acc[16][4];
#pragma unroll
        for (int p = 0; p < 16; ++p)
#pragma unroll
            for (int i = 0; i < 4; ++i) acc[p][i] = 0.f;

#pragma unroll
        for (int kk = 0; kk < 4; ++kk) {
            uint32_t ah[4], al[4];
            {
                int m = lane >> 3, r = lane & 7;
                uint32_t aoff = swz((uint32_t)((w * 16 + (m & 1) * 8 + r) * 128 +
                                               (2 * kk + (m >> 1)) * 16));
                ldsm4(ah[0], ah[1], ah[2], ah[3], sb + SMB_EHI + aoff);
                ldsm4(al[0], al[1], al[2], al[3], sb + SMB_ELO + aoff);
            }
#pragma unroll
            for (int p = 0; p < 8; ++p) {
                uint32_t bh[4], bl[4];
                int m = lane >> 3, r = lane & 7;
                uint32_t boff = swz((uint32_t)((p * 16 + (m >> 1) * 8 + r) * 128 +
                                               (2 * kk + (m & 1)) * 16));
                ldsm4(bh[0], bh[1], bh[2], bh[3], bbase + boff);
                ldsm4(bl[0], bl[1], bl[2], bl[3], bbase + 16384 + boff);
                mma16816(acc[2 * p],     ah, bh[0], bh[1]);
                mma16816(acc[2 * p + 1], ah, bh[2], bh[3]);
                mma16816(acc[2 * p],     ah, bl[0], bl[1]);
                mma16816(acc[2 * p + 1], ah, bl[2], bl[3]);
                mma16816(acc[2 * p],     al, bh[0], bh[1]);
                mma16816(acc[2 * p + 1], al, bh[2], bh[3]);
            }
        }

        // epilogue: +bias, streaming stores, 16 tokens x 128 cols per warp
        const float* sbias = reinterpret_cast<const float*>(smem + SMB_BIAS) + nt * 128;
        float* o0 = out_inj + (size_t)(tok0 + w * 16 + row) * CP_D + nt * 128;
        float* o1 = o0 + 8 * CP_D;
#pragma unroll
        for (int p = 0; p < 16; ++p) {
            int col = p * 8 + tcol;
            float2 bv = *reinterpret_cast<const float2*>(sbias + col);
            __stcs(reinterpret_cast<float2*>(o0 + col),
                   make_float2(acc[p][0] + bv.x, acc[p][1] + bv.y));
            __stcs(reinterpret_cast<float2*>(o1 + col),
                   make_float2(acc[p][2] + bv.x, acc[p][3] + bv.y));
        }
        __syncthreads();
    }
}

// ---------------------------------------------------------------------------
// Launch
// ---------------------------------------------------------------------------
extern "C" void kernel_launch(void* const* d_in, const int* in_sizes, int n_in,
                              void* d_out, int out_size)
{
    const float* x       = (const float*)d_in[0];
    const float* inc_w   = (const float*)d_in[1];
    const float* inc_b   = (const float*)d_in[2];
    const float* reset_w = (const float*)d_in[3];
    const float* reset_b = (const float*)d_in[4];
    const float* read_w  = (const float*)d_in[5];
    const float* read_b  = (const float*)d_in[6];

    float* out        = (float*)d_out;
    float* out_inj    = out;
    float* out_inclog = out + (size_t)CP_BL * CP_D;
    float* out_cnt    = out_inclog + (size_t)CP_BL * CP_K;

    cudaFuncSetAttribute(readout_kernel,
                         cudaFuncAttributeMaxDynamicSharedMemorySize, SM_TOT);

    prep_kernel<<<256, 256>>>(read_w);
    gates_kernel<<<CP_BL / 16, 256>>>(x, inc_w, inc_b, reset_w, reset_b, out_inclog);
    chunkscan_kernel<<<CP_NCHTOT, 256>>>();
    readout_kernel<<<CP_BL / 128, 256, SM_TOT>>>(read_b, out_inj, out_cnt);
}

// round 6
// speedup vs baseline: 2.1812x; 1.0475x over previous
#include <cuda_runtime.h>
#include <cuda_bf16.h>
#include <math.h>
#include <stdint.h>

// Problem constants
#define CP_B      4
#define CP_L      8192
#define CP_D      1024
#define CP_K      2
#define CP_NF     16
#define CP_E      64              // K * 2 * NF
#define CP_BL     (CP_B * CP_L)   // 32768 tokens
#define CP_CHUNK  512
#define CP_NCHUNK (CP_L / CP_CHUNK)        // 16
#define CP_NCHTOT (CP_BL / CP_CHUNK)       // 64

// Scratch (static device globals)
__device__ float4 g_gates[CP_BL];
__device__ float4 g_scan[CP_BL];
__device__ float4 g_agg[CP_NCHTOT];
__device__ float2 g_pre[CP_NCHTOT];
__device__ int    g_sync;                                   // zero-initialized
__device__ __align__(16) __nv_bfloat16 g_Bhi[CP_D * CP_E];  // [n][k], K-major rows of 128B
__device__ __align__(16) __nv_bfloat16 g_Blo[CP_D * CP_E];

__device__ __forceinline__ float4 comb(float4 l, float4 r) {
    float4 o;
    o.x = r.x * l.x;  o.y = fmaf(r.x, l.y, r.y);
    o.z = r.z * l.z;  o.w = fmaf(r.z, l.w, r.w);
    return o;
}

// ---------------- helpers (sm_103 base-target only: no tcgen05) ----------------
__device__ __forceinline__ uint32_t smem_u32(const void* p) {
    uint32_t a;
    asm("{ .reg .u64 t; cvta.to.shared.u64 t, %1; cvt.u32.u64 %0, t; }" : "=r"(a) : "l"(p));
    return a;
}
__device__ __forceinline__ uint32_t swz(uint32_t off) {   // SW128 swizzle (128B rows)
    return off ^ ((off >> 3) & 0x70);
}
__device__ __forceinline__ void ldsm4(uint32_t& r0, uint32_t& r1, uint32_t& r2, uint32_t& r3,
                                      uint32_t addr) {
    asm volatile("ldmatrix.sync.aligned.m8n8.x4.shared.b16 {%0,%1,%2,%3}, [%4];"
                 : "=r"(r0), "=r"(r1), "=r"(r2), "=r"(r3) : "r"(addr));
}
__device__ __forceinline__ void mma16816(float* c, const uint32_t* a, uint32_t b0, uint32_t b1) {
    asm volatile("mma.sync.aligned.m16n8k16.row.col.f32.bf16.bf16.f32 "
                 "{%0,%1,%2,%3}, {%4,%5,%6,%7}, {%8,%9}, {%0,%1,%2,%3};"
                 : "+f"(c[0]), "+f"(c[1]), "+f"(c[2]), "+f"(c[3])
                 : "r"(a[0]), "r"(a[1]), "r"(a[2]), "r"(a[3]), "r"(b0), "r"(b1));
}
__device__ __forceinline__ void cp16(uint32_t dst, const void* src) {
    asm volatile("cp.async.ca.shared.global [%0], [%1], 16;" :: "r"(dst), "l"(src));
}
__device__ __forceinline__ void cp_commit() {
    asm volatile("cp.async.commit_group;" ::: "memory");
}
template <int N>
__device__ __forceinline__ void cp_wait() {
    asm volatile("cp.async.wait_group %0;" :: "n"(N) : "memory");
}

// ---------------------------------------------------------------------------
// Kernel 0: split read_w (64,1024) fp32 -> bf16 hi/lo in [N=1024][K=64].
// ---------------------------------------------------------------------------
__global__ __launch_bounds__(256) void prep_kernel(const float* __restrict__ rw)
{
    int idx = blockIdx.x * 256 + threadIdx.x;   // 0..65535
    int n = idx >> 6, k = idx & 63;
    float v = rw[k * CP_D + n];
    __nv_bfloat16 h = __float2bfloat16(v);
    float res = v - __bfloat162float(h);
    g_Bhi[n * CP_E + k] = h;
    g_Blo[n * CP_E + k] = __float2bfloat16(res);
}

// ---------------------------------------------------------------------------
// Kernel 1: gate projections (x loads use streaming hint)
// ---------------------------------------------------------------------------
__global__ __launch_bounds__(256) void gates_kernel(
    const float* __restrict__ x,
    const float* __restrict__ inc_w, const float* __restrict__ inc_b,
    const float* __restrict__ reset_w, const float* __restrict__ reset_b,
    float* __restrict__ out_inc_logits)
{
    __shared__ __align__(16) float sI0[CP_D], sI1[CP_D], sR0[CP_D], sR1[CP_D];
    int tid = threadIdx.x;
    for (int d = tid; d < CP_D; d += 256) {
        sI0[d] = inc_w[2 * d];     sI1[d] = inc_w[2 * d + 1];
        sR0[d] = reset_w[2 * d];   sR1[d] = reset_w[2 * d + 1];
    }
    __syncthreads();

    int lane = tid & 31;
    int wid  = tid >> 5;
    int tokA = blockIdx.x * 16 + wid * 2;
    int tokB = tokA + 1;

    const float4* xA = reinterpret_cast<const float4*>(x + (size_t)tokA * CP_D);
    const float4* xB = reinterpret_cast<const float4*>(x + (size_t)tokB * CP_D);
    const float4* wI0 = reinterpret_cast<const float4*>(sI0);
    const float4* wI1 = reinterpret_cast<const float4*>(sI1);
    const float4* wR0 = reinterpret_cast<const float4*>(sR0);
    const float4* wR1 = reinterpret_cast<const float4*>(sR1);

    float a0 = 0.f, a1 = 0.f, a2 = 0.f, a3 = 0.f;
    float b0 = 0.f, b1 = 0.f, b2 = 0.f, b3 = 0.f;
#pragma unroll
    for (int i = 0; i < 8; ++i) {
        int i4 = lane + (i << 5);
        float4 xa = __ldcs(&xA[i4]);
        float4 xb = __ldcs(&xB[i4]);
        float4 u = wI0[i4], v = wI1[i4], p = wR0[i4], q = wR1[i4];
        a0 = fmaf(xa.x, u.x, a0); a0 = fmaf(xa.y, u.y, a0);
        a0 = fmaf(xa.z, u.z, a0); a0 = fmaf(xa.w, u.w, a0);
        a1 = fmaf(xa.x, v.x, a1); a1 = fmaf(xa.y, v.y, a1);
        a1 = fmaf(xa.z, v.z, a1); a1 = fmaf(xa.w, v.w, a1);
        a2 = fmaf(xa.x, p.x, a2); a2 = fmaf(xa.y, p.y, a2);
        a2 = fmaf(xa.z, p.z, a2); a2 = fmaf(xa.w, p.w, a2);
        a3 = fmaf(xa.x, q.x, a3); a3 = fmaf(xa.y, q.y, a3);
        a3 = fmaf(xa.z, q.z, a3); a3 = fmaf(xa.w, q.w, a3);
        b0 = fmaf(xb.x, u.x, b0); b0 = fmaf(xb.y, u.y, b0);
        b0 = fmaf(xb.z, u.z, b0); b0 = fmaf(xb.w, u.w, b0);
        b1 = fmaf(xb.x, v.x, b1); b1 = fmaf(xb.y, v.y, b1);
        b1 = fmaf(xb.z, v.z, b1); b1 = fmaf(xb.w, v.w, b1);
        b2 = fmaf(xb.x, p.x, b2); b2 = fmaf(xb.y, p.y, b2);
        b2 = fmaf(xb.z, p.z, b2); b2 = fmaf(xb.w, p.w, b2);
        b3 = fmaf(xb.x, q.x, b3); b3 = fmaf(xb.y, q.y, b3);
        b3 = fmaf(xb.z, q.z, b3); b3 = fmaf(xb.w, q.w, b3);
    }
#pragma unroll
    for (int off = 16; off > 0; off >>= 1) {
        a0 += __shfl_xor_sync(0xffffffffu, a0, off);
        a1 += __shfl_xor_sync(0xffffffffu, a1, off);
        a2 += __shfl_xor_sync(0xffffffffu, a2, off);
        a3 += __shfl_xor_sync(0xffffffffu, a3, off);
        b0 += __shfl_xor_sync(0xffffffffu, b0, off);
        b1 += __shfl_xor_sync(0xffffffffu, b1, off);
        b2 += __shfl_xor_sync(0xffffffffu, b2, off);
        b3 += __shfl_xor_sync(0xffffffffu, b3, off);
    }
    if (lane == 0) {
        float ib0 = inc_b[0], ib1 = inc_b[1], rb0 = reset_b[0], rb1 = reset_b[1];
        float ilA0 = a0 + ib0, ilA1 = a1 + ib1;
        float rlA0 = a2 + rb0, rlA1 = a3 + rb1;
        reinterpret_cast<float2*>(out_inc_logits)[tokA] = make_float2(ilA0, ilA1);
        g_gates[tokA] = make_float4(1.f / (1.f + expf(rlA0)),
                                    1.f / (1.f + expf(-ilA0)),
                                    1.f / (1.f + expf(rlA1)),
                                    1.f / (1.f + expf(-ilA1)));
        float ilB0 = b0 + ib0, ilB1 = b1 + ib1;
        float rlB0 = b2 + rb0, rlB1 = b3 + rb1;
        reinterpret_cast<float2*>(out_inc_logits)[tokB] = make_float2(ilB0, ilB1);
        g_gates[tokB] = make_float4(1.f / (1.f + expf(rlB0)),
                                    1.f / (1.f + expf(-ilB0)),
                                    1.f / (1.f + expf(rlB1)),
                                    1.f / (1.f + expf(-ilB1)));
    }
}

// ---------------------------------------------------------------------------
// Kernel 2: per-chunk inclusive scan + fused aggregate scan in the tail.
// ---------------------------------------------------------------------------
__global__ __launch_bounds__(256) void chunkscan_kernel()
{
    __shared__ float4 wagg[8];
    __shared__ float4 wexc[8];
    __shared__ int s_last;
    int t = threadIdx.x, lane = t & 31, wid = t >> 5;
    int tok = blockIdx.x * CP_CHUNK + 2 * t;

    float4 a = g_gates[tok];
    float4 b = g_gates[tok + 1];
    float4 s = comb(a, b);

#pragma unroll
    for (int off = 1; off < 32; off <<= 1) {
        float4 l;
        l.x = __shfl_up_sync(0xffffffffu, s.x, off);
        l.y = __shfl_up_sync(0xffffffffu, s.y, off);
        l.z = __shfl_up_sync(0xffffffffu, s.z, off);
        l.w = __shfl_up_sync(0xffffffffu, s.w, off);
        if (lane >= off) s = comb(l, s);
    }
    if (lane == 31) wagg[wid] = s;
    __syncthreads();

    if (wid == 0) {
        float4 v = (lane < 8) ? wagg[lane] : make_float4(1.f, 0.f, 1.f, 0.f);
#pragma unroll
        for (int off = 1; off < 8; off <<= 1) {
            float4 l;
            l.x = __shfl_up_sync(0xffffffffu, v.x, off);
            l.y = __shfl_up_sync(0xffffffffu, v.y, off);
            l.z = __shfl_up_sync(0xffffffffu, v.z, off);
            l.w = __shfl_up_sync(0xffffffffu, v.w, off);
            if (lane >= off && lane < 8) v = comb(l, v);
        }
        if (lane == 0) wexc[0] = make_float4(1.f, 0.f, 1.f, 0.f);
        if (lane < 7)  wexc[lane + 1] = v;
    }
    __syncthreads();

    float4 se;
    {
        float4 l;
        l.x = __shfl_up_sync(0xffffffffu, s.x, 1);
        l.y = __shfl_up_sync(0xffffffffu, s.y, 1);
        l.z = __shfl_up_sync(0xffffffffu, s.z, 1);
        l.w = __shfl_up_sync(0xffffffffu, s.w, 1);
        se = (lane == 0) ? make_float4(1.f, 0.f, 1.f, 0.f) : l;
    }
    float4 P = comb(wexc[wid], se);
    float4 o0 = comb(P, a);
    float4 o1 = comb(o0, b);
    g_scan[tok]     = o0;
    g_scan[tok + 1] = o1;
    if (t == 255) g_agg[blockIdx.x] = o1;

    __threadfence();
    __syncthreads();
    if (t == 0) {
        int prev = atomicAdd(&g_sync, 1);
        s_last = (prev == CP_NCHTOT - 1);
    }
    __syncthreads();
    if (s_last) {
        if (t < CP_B) {
            float c0 = 0.f, c1 = 0.f;
            for (int j = 0; j < CP_NCHUNK; ++j) {
                g_pre[t * CP_NCHUNK + j] = make_float2(c0, c1);
                float4 ag = g_agg[t * CP_NCHUNK + j];
                c0 = fmaf(ag.x, c0, ag.y);
                c1 = fmaf(ag.z, c1, ag.w);
            }
        }
        if (t == 0) g_sync = 0;
    }
}

// ---------------------------------------------------------------------------
// Kernel 4: counters + embedding + mma.sync bf16x3 GEMM + bias.
// 8 warps as 4 (m) x 2 (n): warp = 32 tokens x 64 cols per 128-col N-chunk.
// Cuts per-warp B LDSM duplication 8x -> 4x (72 -> 48 ldsm4/warp/chunk).
// ---------------------------------------------------------------------------
#define SMB_BIAS  0
#define SMB_EHI   4096
#define SMB_ELO   20480
#define SMB_B     36864
#define SMB_BUF   32768
#define SM_TOT    (SMB_B + 2 * SMB_BUF)   // 102400

__device__ __forceinline__ void stage_B(uint32_t sb, int nt, int buf, int tid)
{
    const char* srcH = (const char*)g_Bhi + (size_t)nt * 128 * 128;
    const char* srcL = (const char*)g_Blo + (size_t)nt * 128 * 128;
    uint32_t dstH = sb + SMB_B + buf * SMB_BUF;
    uint32_t dstL = dstH + 16384;
#pragma unroll
    for (int m = 0; m < 4; ++m) {
        int idx = tid + m * 256;          // 0..1023
        int nl = idx >> 3, c16 = idx & 7;
        uint32_t sw = swz((uint32_t)(nl * 128 + c16 * 16));
        cp16(dstH + sw, srcH + nl * 128 + c16 * 16);
        cp16(dstL + sw, srcL + nl * 128 + c16 * 16);
    }
}

__global__ __launch_bounds__(256, 2) void readout_kernel(
    const float* __restrict__ read_b,
    float* __restrict__ out_inj,        // (B*L, 1024)
    float* __restrict__ out_counters)   // (B*L, 2)
{
    extern __shared__ __align__(1024) char smem[];
    uint32_t sb = smem_u32(smem);
    int tid = threadIdx.x, lane = tid & 31, w = tid >> 5;
    int wy = w >> 1, wx = w & 1;        // 4 m-groups x 2 n-groups
    int tok0 = blockIdx.x * 128;

    // bias -> smem (256 * 16B = 4KB)
    reinterpret_cast<float4*>(smem + SMB_BIAS)[tid] =
        reinterpret_cast<const float4*>(read_b)[tid];

    // ---- counters + embedding -> bf16 hi/lo swizzled tiles [128 x 64] ----
    {
        int t   = tid >> 1;
        int k   = tid & 1;
        int tok = tok0 + t;
        int b   = tok / CP_L;
        int jc  = (tok % CP_L) / CP_CHUNK;
        float2 pre = g_pre[b * CP_NCHUNK + jc];
        float4 sc  = g_scan[tok];
        float pk = k ? sc.z : sc.x;
        float pi = k ? sc.w : sc.y;
        float pp = k ? pre.y : pre.x;
        float c  = fmaf(pk, pp, pi);
        out_counters[tok * 2 + k] = c;

        float sv[16], cv[16];
#pragma unroll
        for (int f = 0; f < CP_NF; ++f) {
            float invf = exp2f(-12.0f * (float)f / 15.0f);
            sincosf(c * invf, &sv[f], &cv[f]);
        }
#pragma unroll
        for (int q = 0; q < 8; ++q) {     // 8B = 4 bf16 per store
            unsigned long long hi = 0ull, lo = 0ull;
#pragma unroll
            for (int bq = 0; bq < 4; ++bq) {
                int j = 4 * q + bq;
                float v = (j < 16) ? sv[j] : cv[j - 16];
                __nv_bfloat16 h = __float2bfloat16(v);
                float res = v - __bfloat162float(h);
                __nv_bfloat16 l = __float2bfloat16(res);
                hi |= (unsigned long long)__bfloat16_as_ushort(h) << (16 * bq);
                lo |= (unsigned long long)__bfloat16_as_ushort(l) << (16 * bq);
            }
            uint32_t off = (uint32_t)(t * 128 + k * 64 + q * 8);
            uint32_t sw = swz(off);
            *reinterpret_cast<unsigned long long*>(smem + SMB_EHI + sw) = hi;
            *reinterpret_cast<unsigned long long*>(smem + SMB_ELO + sw) = lo;
        }
    }

    // prefetch B chunk 0
    stage_B(sb, 0, 0, tid);
    cp_commit();

    int row = lane >> 2, tcol = 2 * (lane & 3);
    int mlsb = lane >> 3, r8 = lane & 7;    // ldmatrix addressing

#pragma unroll 1
    for (int nt = 0; nt < 8; ++nt) {
        int buf = nt & 1;
        if (nt < 7) {
            stage_B(sb, nt + 1, buf ^ 1, tid);
            cp_commit();
            cp_wait<1>();
        } else {
            cp_wait<0>();
        }
        __syncthreads();

        uint32_t bbase = sb + SMB_B + buf * SMB_BUF;
        float acc[2][8][4];
#pragma unroll
        for (int mt = 0; mt < 2; ++mt)
#pragma unroll
            for (int p = 0; p < 8; ++p)
#pragma unroll
                for (int i = 0; i < 4; ++i) acc[mt][p][i] = 0.f;

#pragma unroll
        for (int kk = 0; kk < 4; ++kk) {
            uint32_t ah[2][4], al[2][4];
#pragma unroll
            for (int mt = 0; mt < 2; ++mt) {
                uint32_t aoff = swz((uint32_t)((wy * 32 + mt * 16 + (mlsb & 1) * 8 + r8) * 128 +
                                               (2 * kk + (mlsb >> 1)) * 16));
                ldsm4(ah[mt][0], ah[mt][1], ah[mt][2], ah[mt][3], sb + SMB_EHI + aoff);
                ldsm4(al[mt][0], al[mt][1], al[mt][2], al[mt][3], sb + SMB_ELO + aoff);
            }
#pragma unroll
            for (int p4 = 0; p4 < 4; ++p4) {
                int pg = wx * 4 + p4;       // 16-col group 0..7 within chunk
                uint32_t bh[4], bl[4];
                uint32_t boff = swz((uint32_t)((pg * 16 + (mlsb >> 1) * 8 + r8) * 128 +
                                               (2 * kk + (mlsb & 1)) * 16));
                ldsm4(bh[0], bh[1], bh[2], bh[3], bbase + boff);
                ldsm4(bl[0], bl[1], bl[2], bl[3], bbase + 16384 + boff);
#pragma unroll
                for (int mt = 0; mt < 2; ++mt) {
                    mma16816(acc[mt][2 * p4],     ah[mt], bh[0], bh[1]);
                    mma16816(acc[mt][2 * p4 + 1], ah[mt], bh[2], bh[3]);
                    mma16816(acc[mt][2 * p4],     ah[mt], bl[0], bl[1]);
                    mma16816(acc[mt][2 * p4 + 1], ah[mt], bl[2], bl[3]);
                    mma16816(acc[mt][2 * p4],     al[mt], bh[0], bh[1]);
                    mma16816(acc[mt][2 * p4 + 1], al[mt], bh[2], bh[3]);
                }
            }
        }

        // epilogue: +bias, streaming stores; warp = 32 tokens x 64 cols
        const float* sbias = reinterpret_cast<const float*>(smem + SMB_BIAS) +
                             nt * 128 + wx * 64;
#pragma unroll
        for (int mt = 0; mt < 2; ++mt) {
            float* o0 = out_inj + (size_t)(tok0 + wy * 32 + mt * 16 + row) * CP_D +
                        nt * 128 + wx * 64;
            float* o1 = o0 + 8 * CP_D;
#pragma unroll
            for (int p = 0; p < 8; ++p) {
                int col = p * 8 + tcol;
                float2 bv = *reinterpret_cast<const float2*>(sbias + col);
                __stcs(reinterpret_cast<float2*>(o0 + col),
                       make_float2(acc[mt][p][0] + bv.x, acc[mt][p][1] + bv.y));
                __stcs(reinterpret_cast<float2*>(o1 + col),
                       make_float2(acc[mt][p][2] + bv.x, acc[mt][p][3] + bv.y));
            }
        }
        __syncthreads();
    }
}

// ---------------------------------------------------------------------------
// Launch
// ---------------------------------------------------------------------------
extern "C" void kernel_launch(void* const* d_in, const int* in_sizes, int n_in,
                              void* d_out, int out_size)
{
    const float* x       = (const float*)d_in[0];
    const float* inc_w   = (const float*)d_in[1];
    const float* inc_b   = (const float*)d_in[2];
    const float* reset_w = (const float*)d_in[3];
    const float* reset_b = (const float*)d_in[4];
    const float* read_w  = (const float*)d_in[5];
    const float* read_b  = (const float*)d_in[6];

    float* out        = (float*)d_out;
    float* out_inj    = out;
    float* out_inclog = out + (size_t)CP_BL * CP_D;
    float* out_cnt    = out_inclog + (size_t)CP_BL * CP_K;

    cudaFuncSetAttribute(readout_kernel,
                         cudaFuncAttributeMaxDynamicSharedMemorySize, SM_TOT);

    prep_kernel<<<256, 256>>>(read_w);
    gates_kernel<<<CP_BL / 16, 256>>>(x, inc_w, inc_b, reset_w, reset_b, out_inclog);
    chunkscan_kernel<<<CP_NCHTOT, 256>>>();
    readout_kernel<<<CP_BL / 128, 256, SM_TOT>>>(read_b, out_inj, out_cnt);
}

// round 7
// speedup vs baseline: 2.2196x; 1.0176x over previous
#include <cuda_runtime.h>
#include <cuda_bf16.h>
#include <math.h>
#include <stdint.h>

// Problem constants
#define CP_B      4
#define CP_L      8192
#define CP_D      1024
#define CP_K      2
#define CP_NF     16
#define CP_E      64              // K * 2 * NF
#define CP_BL     (CP_B * CP_L)   // 32768 tokens
#define CP_CHUNK  512
#define CP_NCHUNK (CP_L / CP_CHUNK)        // 16
#define CP_NCHTOT (CP_BL / CP_CHUNK)       // 64

// Scratch (static device globals)
__device__ float4 g_gates[CP_BL];
__device__ float4 g_scan[CP_BL];
__device__ float4 g_agg[CP_NCHTOT];
__device__ float2 g_pre[CP_NCHTOT];
__device__ int    g_sync;                                   // zero-initialized
__device__ __align__(16) __nv_bfloat16 g_Bhi[CP_D * CP_E];  // [n][k], K-major rows of 128B
__device__ __align__(16) __nv_bfloat16 g_Blo[CP_D * CP_E];

__device__ __forceinline__ float4 comb(float4 l, float4 r) {
    float4 o;
    o.x = r.x * l.x;  o.y = fmaf(r.x, l.y, r.y);
    o.z = r.z * l.z;  o.w = fmaf(r.z, l.w, r.w);
    return o;
}

// ---------------- helpers (sm_103 base-target only: no tcgen05) ----------------
__device__ __forceinline__ uint32_t smem_u32(const void* p) {
    uint32_t a;
    asm("{ .reg .u64 t; cvta.to.shared.u64 t, %1; cvt.u32.u64 %0, t; }" : "=r"(a) : "l"(p));
    return a;
}
__device__ __forceinline__ uint32_t swz(uint32_t off) {   // SW128 swizzle (128B rows)
    return off ^ ((off >> 3) & 0x70);
}
__device__ __forceinline__ void ldsm4(uint32_t& r0, uint32_t& r1, uint32_t& r2, uint32_t& r3,
                                      uint32_t addr) {
    asm volatile("ldmatrix.sync.aligned.m8n8.x4.shared.b16 {%0,%1,%2,%3}, [%4];"
                 : "=r"(r0), "=r"(r1), "=r"(r2), "=r"(r3) : "r"(addr));
}
__device__ __forceinline__ void mma16816(float* c, const uint32_t* a, uint32_t b0, uint32_t b1) {
    asm volatile("mma.sync.aligned.m16n8k16.row.col.f32.bf16.bf16.f32 "
                 "{%0,%1,%2,%3}, {%4,%5,%6,%7}, {%8,%9}, {%0,%1,%2,%3};"
                 : "+f"(c[0]), "+f"(c[1]), "+f"(c[2]), "+f"(c[3])
                 : "r"(a[0]), "r"(a[1]), "r"(a[2]), "r"(a[3]), "r"(b0), "r"(b1));
}
__device__ __forceinline__ void cp16(uint32_t dst, const void* src) {
    asm volatile("cp.async.ca.shared.global [%0], [%1], 16;" :: "r"(dst), "l"(src));
}
__device__ __forceinline__ void cp_commit() {
    asm volatile("cp.async.commit_group;" ::: "memory");
}
template <int N>
__device__ __forceinline__ void cp_wait() {
    asm volatile("cp.async.wait_group %0;" :: "n"(N) : "memory");
}

// ---------------------------------------------------------------------------
// Kernel 0: split read_w (64,1024) fp32 -> bf16 hi/lo in [N=1024][K=64].
// ---------------------------------------------------------------------------
__global__ __launch_bounds__(256) void prep_kernel(const float* __restrict__ rw)
{
    int idx = blockIdx.x * 256 + threadIdx.x;   // 0..65535
    int n = idx >> 6, k = idx & 63;
    float v = rw[k * CP_D + n];
    __nv_bfloat16 h = __float2bfloat16(v);
    float res = v - __bfloat162float(h);
    g_Bhi[n * CP_E + k] = h;
    g_Blo[n * CP_E + k] = __float2bfloat16(res);
}

// ---------------------------------------------------------------------------
// Kernel 1: gate projections (x loads use streaming hint)
// ---------------------------------------------------------------------------
__global__ __launch_bounds__(256) void gates_kernel(
    const float* __restrict__ x,
    const float* __restrict__ inc_w, const float* __restrict__ inc_b,
    const float* __restrict__ reset_w, const float* __restrict__ reset_b,
    float* __restrict__ out_inc_logits)
{
    __shared__ __align__(16) float sI0[CP_D], sI1[CP_D], sR0[CP_D], sR1[CP_D];
    int tid = threadIdx.x;
    for (int d = tid; d < CP_D; d += 256) {
        sI0[d] = inc_w[2 * d];     sI1[d] = inc_w[2 * d + 1];
        sR0[d] = reset_w[2 * d];   sR1[d] = reset_w[2 * d + 1];
    }
    __syncthreads();

    int lane = tid & 31;
    int wid  = tid >> 5;
    int tokA = blockIdx.x * 16 + wid * 2;
    int tokB = tokA + 1;

    const float4* xA = reinterpret_cast<const float4*>(x + (size_t)tokA * CP_D);
    const float4* xB = reinterpret_cast<const float4*>(x + (size_t)tokB * CP_D);
    const float4* wI0 = reinterpret_cast<const float4*>(sI0);
    const float4* wI1 = reinterpret_cast<const float4*>(sI1);
    const float4* wR0 = reinterpret_cast<const float4*>(sR0);
    const float4* wR1 = reinterpret_cast<const float4*>(sR1);

    float a0 = 0.f, a1 = 0.f, a2 = 0.f, a3 = 0.f;
    float b0 = 0.f, b1 = 0.f, b2 = 0.f, b3 = 0.f;
#pragma unroll
    for (int i = 0; i < 8; ++i) {
        int i4 = lane + (i << 5);
        float4 xa = __ldcs(&xA[i4]);
        float4 xb = __ldcs(&xB[i4]);
        float4 u = wI0[i4], v = wI1[i4], p = wR0[i4], q = wR1[i4];
        a0 = fmaf(xa.x, u.x, a0); a0 = fmaf(xa.y, u.y, a0);
        a0 = fmaf(xa.z, u.z, a0); a0 = fmaf(xa.w, u.w, a0);
        a1 = fmaf(xa.x, v.x, a1); a1 = fmaf(xa.y, v.y, a1);
        a1 = fmaf(xa.z, v.z, a1); a1 = fmaf(xa.w, v.w, a1);
        a2 = fmaf(xa.x, p.x, a2); a2 = fmaf(xa.y, p.y, a2);
        a2 = fmaf(xa.z, p.z, a2); a2 = fmaf(xa.w, p.w, a2);
        a3 = fmaf(xa.x, q.x, a3); a3 = fmaf(xa.y, q.y, a3);
        a3 = fmaf(xa.z, q.z, a3); a3 = fmaf(xa.w, q.w, a3);
        b0 = fmaf(xb.x, u.x, b0); b0 = fmaf(xb.y, u.y, b0);
        b0 = fmaf(xb.z, u.z, b0); b0 = fmaf(xb.w, u.w, b0);
        b1 = fmaf(xb.x, v.x, b1); b1 = fmaf(xb.y, v.y, b1);
        b1 = fmaf(xb.z, v.z, b1); b1 = fmaf(xb.w, v.w, b1);
        b2 = fmaf(xb.x, p.x, b2); b2 = fmaf(xb.y, p.y, b2);
        b2 = fmaf(xb.z, p.z, b2); b2 = fmaf(xb.w, p.w, b2);
        b3 = fmaf(xb.x, q.x, b3); b3 = fmaf(xb.y, q.y, b3);
        b3 = fmaf(xb.z, q.z, b3); b3 = fmaf(xb.w, q.w, b3);
    }
#pragma unroll
    for (int off = 16; off > 0; off >>= 1) {
        a0 += __shfl_xor_sync(0xffffffffu, a0, off);
        a1 += __shfl_xor_sync(0xffffffffu, a1, off);
        a2 += __shfl_xor_sync(0xffffffffu, a2, off);
        a3 += __shfl_xor_sync(0xffffffffu, a3, off);
        b0 += __shfl_xor_sync(0xffffffffu, b0, off);
        b1 += __shfl_xor_sync(0xffffffffu, b1, off);
        b2 += __shfl_xor_sync(0xffffffffu, b2, off);
        b3 += __shfl_xor_sync(0xffffffffu, b3, off);
    }
    if (lane == 0) {
        float ib0 = inc_b[0], ib1 = inc_b[1], rb0 = reset_b[0], rb1 = reset_b[1];
        float ilA0 = a0 + ib0, ilA1 = a1 + ib1;
        float rlA0 = a2 + rb0, rlA1 = a3 + rb1;
        reinterpret_cast<float2*>(out_inc_logits)[tokA] = make_float2(ilA0, ilA1);
        g_gates[tokA] = make_float4(1.f / (1.f + expf(rlA0)),
                                    1.f / (1.f + expf(-ilA0)),
                                    1.f / (1.f + expf(rlA1)),
                                    1.f / (1.f + expf(-ilA1)));
        float ilB0 = b0 + ib0, ilB1 = b1 + ib1;
        float rlB0 = b2 + rb0, rlB1 = b3 + rb1;
        reinterpret_cast<float2*>(out_inc_logits)[tokB] = make_float2(ilB0, ilB1);
        g_gates[tokB] = make_float4(1.f / (1.f + expf(rlB0)),
                                    1.f / (1.f + expf(-ilB0)),
                                    1.f / (1.f + expf(rlB1)),
                                    1.f / (1.f + expf(-ilB1)));
    }
}

// ---------------------------------------------------------------------------
// Kernel 2: per-chunk inclusive scan + fused aggregate scan in the tail.
// ---------------------------------------------------------------------------
__global__ __launch_bounds__(256) void chunkscan_kernel()
{
    __shared__ float4 wagg[8];
    __shared__ float4 wexc[8];
    __shared__ int s_last;
    int t = threadIdx.x, lane = t & 31, wid = t >> 5;
    int tok = blockIdx.x * CP_CHUNK + 2 * t;

    float4 a = g_gates[tok];
    float4 b = g_gates[tok + 1];
    float4 s = comb(a, b);

#pragma unroll
    for (int off = 1; off < 32; off <<= 1) {
        float4 l;
        l.x = __shfl_up_sync(0xffffffffu, s.x, off);
        l.y = __shfl_up_sync(0xffffffffu, s.y, off);
        l.z = __shfl_up_sync(0xffffffffu, s.z, off);
        l.w = __shfl_up_sync(0xffffffffu, s.w, off);
        if (lane >= off) s = comb(l, s);
    }
    if (lane == 31) wagg[wid] = s;
    __syncthreads();

    if (wid == 0) {
        float4 v = (lane < 8) ? wagg[lane] : make_float4(1.f, 0.f, 1.f, 0.f);
#pragma unroll
        for (int off = 1; off < 8; off <<= 1) {
            float4 l;
            l.x = __shfl_up_sync(0xffffffffu, v.x, off);
            l.y = __shfl_up_sync(0xffffffffu, v.y, off);
            l.z = __shfl_up_sync(0xffffffffu, v.z, off);
            l.w = __shfl_up_sync(0xffffffffu, v.w, off);
            if (lane >= off && lane < 8) v = comb(l, v);
        }
        if (lane == 0) wexc[0] = make_float4(1.f, 0.f, 1.f, 0.f);
        if (lane < 7)  wexc[lane + 1] = v;
    }
    __syncthreads();

    float4 se;
    {
        float4 l;
        l.x = __shfl_up_sync(0xffffffffu, s.x, 1);
        l.y = __shfl_up_sync(0xffffffffu, s.y, 1);
        l.z = __shfl_up_sync(0xffffffffu, s.z, 1);
        l.w = __shfl_up_sync(0xffffffffu, s.w, 1);
        se = (lane == 0) ? make_float4(1.f, 0.f, 1.f, 0.f) : l;
    }
    float4 P = comb(wexc[wid], se);
    float4 o0 = comb(P, a);
    float4 o1 = comb(o0, b);
    g_scan[tok]     = o0;
    g_scan[tok + 1] = o1;
    if (t == 255) g_agg[blockIdx.x] = o1;

    __threadfence();
    __syncthreads();
    if (t == 0) {
        int prev = atomicAdd(&g_sync, 1);
        s_last = (prev == CP_NCHTOT - 1);
    }
    __syncthreads();
    if (s_last) {
        if (t < CP_B) {
            float c0 = 0.f, c1 = 0.f;
            for (int j = 0; j < CP_NCHUNK; ++j) {
                g_pre[t * CP_NCHUNK + j] = make_float2(c0, c1);
                float4 ag = g_agg[t * CP_NCHUNK + j];
                c0 = fmaf(ag.x, c0, ag.y);
                c1 = fmaf(ag.z, c1, ag.w);
            }
        }
        if (t == 0) g_sync = 0;
    }
}

// ---------------------------------------------------------------------------
// Kernel 4: counters + embedding + mma.sync bf16x3 GEMM + bias.
// 64-col N-chunks (16 of them), warps 4m x 2n: warp = 32 tokens x 32 cols.
// acc = 32 regs -> ~75 regs total -> 3 blocks/SM (24 warps) for latency hiding.
// ---------------------------------------------------------------------------
#define SMB_BIAS  0
#define SMB_EHI   4096
#define SMB_ELO   20480
#define SMB_B     36864
#define SMB_BUF   16384
#define SM_TOT    (SMB_B + 2 * SMB_BUF)   // 69632

__device__ __forceinline__ void stage_B(uint32_t sb, int nt, int buf, int tid)
{
    const char* srcH = (const char*)g_Bhi + (size_t)nt * 64 * 128;
    const char* srcL = (const char*)g_Blo + (size_t)nt * 64 * 128;
    uint32_t dstH = sb + SMB_B + buf * SMB_BUF;
    uint32_t dstL = dstH + 8192;
#pragma unroll
    for (int m = 0; m < 2; ++m) {
        int idx = tid + m * 256;          // 0..511
        int nl = idx >> 3, c16 = idx & 7;
        uint32_t sw = swz((uint32_t)(nl * 128 + c16 * 16));
        cp16(dstH + sw, srcH + nl * 128 + c16 * 16);
        cp16(dstL + sw, srcL + nl * 128 + c16 * 16);
    }
}

__global__ __launch_bounds__(256, 3) void readout_kernel(
    const float* __restrict__ read_b,
    float* __restrict__ out_inj,        // (B*L, 1024)
    float* __restrict__ out_counters)   // (B*L, 2)
{
    extern __shared__ __align__(1024) char smem[];
    uint32_t sb = smem_u32(smem);
    int tid = threadIdx.x, lane = tid & 31, w = tid >> 5;
    int wy = w >> 1, wx = w & 1;        // 4 m-groups x 2 n-groups
    int tok0 = blockIdx.x * 128;

    // bias -> smem (256 * 16B = 4KB)
    reinterpret_cast<float4*>(smem + SMB_BIAS)[tid] =
        reinterpret_cast<const float4*>(read_b)[tid];

    // ---- counters + embedding -> bf16 hi/lo swizzled tiles [128 x 64] ----
    {
        int t   = tid >> 1;
        int k   = tid & 1;
        int tok = tok0 + t;
        int b   = tok / CP_L;
        int jc  = (tok % CP_L) / CP_CHUNK;
        float2 pre = g_pre[b * CP_NCHUNK + jc];
        float4 sc  = g_scan[tok];
        float pk = k ? sc.z : sc.x;
        float pi = k ? sc.w : sc.y;
        float pp = k ? pre.y : pre.x;
        float c  = fmaf(pk, pp, pi);
        out_counters[tok * 2 + k] = c;

        float sv[16], cv[16];
#pragma unroll
        for (int f = 0; f < CP_NF; ++f) {
            float invf = exp2f(-12.0f * (float)f / 15.0f);
            sincosf(c * invf, &sv[f], &cv[f]);
        }
#pragma unroll
        for (int q = 0; q < 8; ++q) {     // 8B = 4 bf16 per store
            unsigned long long hi = 0ull, lo = 0ull;
#pragma unroll
            for (int bq = 0; bq < 4; ++bq) {
                int j = 4 * q + bq;
                float v = (j < 16) ? sv[j] : cv[j - 16];
                __nv_bfloat16 h = __float2bfloat16(v);
                float res = v - __bfloat162float(h);
                __nv_bfloat16 l = __float2bfloat16(res);
                hi |= (unsigned long long)__bfloat16_as_ushort(h) << (16 * bq);
                lo |= (unsigned long long)__bfloat16_as_ushort(l) << (16 * bq);
            }
            uint32_t off = (uint32_t)(t * 128 + k * 64 + q * 8);
            uint32_t sw = swz(off);
            *reinterpret_cast<unsigned long long*>(smem + SMB_EHI + sw) = hi;
            *reinterpret_cast<unsigned long long*>(smem + SMB_ELO + sw) = lo;
        }
    }

    // prefetch B chunk 0
    stage_B(sb, 0, 0, tid);
    cp_commit();

    int row = lane >> 2, tcol = 2 * (lane & 3);
    int mlsb = lane >> 3, r8 = lane & 7;    // ldmatrix addressing

#pragma unroll 1
    for (int nt = 0; nt < 16; ++nt) {
        int buf = nt & 1;
        if (nt < 15) {
            stage_B(sb, nt + 1, buf ^ 1, tid);
            cp_commit();
            cp_wait<1>();
        } else {
            cp_wait<0>();
        }
        __syncthreads();

        uint32_t bbase = sb + SMB_B + buf * SMB_BUF;
        float acc[2][4][4];
#pragma unroll
        for (int mt = 0; mt < 2; ++mt)
#pragma unroll
            for (int p = 0; p < 4; ++p)
#pragma unroll
                for (int i = 0; i < 4; ++i) acc[mt][p][i] = 0.f;

#pragma unroll
        for (int kk = 0; kk < 4; ++kk) {
            uint32_t ah[2][4], al[2][4];
#pragma unroll
            for (int mt = 0; mt < 2; ++mt) {
                uint32_t aoff = swz((uint32_t)((wy * 32 + mt * 16 + (mlsb & 1) * 8 + r8) * 128 +
                                               (2 * kk + (mlsb >> 1)) * 16));
                ldsm4(ah[mt][0], ah[mt][1], ah[mt][2], ah[mt][3], sb + SMB_EHI + aoff);
                ldsm4(al[mt][0], al[mt][1], al[mt][2], al[mt][3], sb + SMB_ELO + aoff);
            }
#pragma unroll
            for (int p4 = 0; p4 < 2; ++p4) {
                int pg = wx * 2 + p4;       // 16-col group 0..3 within chunk
                uint32_t bh[4], bl[4];
                uint32_t boff = swz((uint32_t)((pg * 16 + (mlsb >> 1) * 8 + r8) * 128 +
                                               (2 * kk + (mlsb & 1)) * 16));
                ldsm4(bh[0], bh[1], bh[2], bh[3], bbase + boff);
                ldsm4(bl[0], bl[1], bl[2], bl[3], bbase + 8192 + boff);
#pragma unroll
                for (int mt = 0; mt < 2; ++mt) {
                    mma16816(acc[mt][2 * p4],     ah[mt], bh[0], bh[1]);
                    mma16816(acc[mt][2 * p4 + 1], ah[mt], bh[2], bh[3]);
                    mma16816(acc[mt][2 * p4],     ah[mt], bl[0], bl[1]);
                    mma16816(acc[mt][2 * p4 + 1], ah[mt], bl[2], bl[3]);
                    mma16816(acc[mt][2 * p4],     al[mt], bh[0], bh[1]);
                    mma16816(acc[mt][2 * p4 + 1], al[mt], bh[2], bh[3]);
                }
            }
        }

        // epilogue: +bias, streaming stores; warp = 32 tokens x 32 cols
        const float* sbias = reinterpret_cast<const float*>(smem + SMB_BIAS) +
                             nt * 64 + wx * 32;
#pragma unroll
        for (int mt = 0; mt < 2; ++mt) {
            float* o0 = out_inj + (size_t)(tok0 + wy * 32 + mt * 16 + row) * CP_D +
                        nt * 64 + wx * 32;
            float* o1 = o0 + 8 * CP_D;
#pragma unroll
            for (int p = 0; p < 4; ++p) {
                int col = p * 8 + tcol;
                float2 bv = *reinterpret_cast<const float2*>(sbias + col);
                __stcs(reinterpret_cast<float2*>(o0 + col),
                       make_float2(acc[mt][p][0] + bv.x, acc[mt][p][1] + bv.y));
                __stcs(reinterpret_cast<float2*>(o1 + col),
                       make_float2(acc[mt][p][2] + bv.x, acc[mt][p][3] + bv.y));
            }
        }
        __syncthreads();
    }
}

// ---------------------------------------------------------------------------
// Launch
// ---------------------------------------------------------------------------
extern "C" void kernel_launch(void* const* d_in, const int* in_sizes, int n_in,
                              void* d_out, int out_size)
{
    const float* x       = (const float*)d_in[0];
    const float* inc_w   = (const float*)d_in[1];
    const float* inc_b   = (const float*)d_in[2];
    const float* reset_w = (const float*)d_in[3];
    const float* reset_b = (const float*)d_in[4];
    const float* read_w  = (const float*)d_in[5];
    const float* read_b  = (const float*)d_in[6];

    float* out        = (float*)d_out;
    float* out_inj    = out;
    float* out_inclog = out + (size_t)CP_BL * CP_D;
    float* out_cnt    = out_inclog + (size_t)CP_BL * CP_K;

    cudaFuncSetAttribute(readout_kernel,
                         cudaFuncAttributeMaxDynamicSharedMemorySize, SM_TOT);

    prep_kernel<<<256, 256>>>(read_w);
    gates_kernel<<<CP_BL / 16, 256>>>(x, inc_w, inc_b, reset_w, reset_b, out_inclog);
    chunkscan_kernel<<<CP_NCHTOT, 256>>>();
    readout_kernel<<<CP_BL / 128, 256, SM_TOT>>>(read_b, out_inj, out_cnt);
}